// round 5
// baseline (speedup 1.0000x reference)
#include <cuda_runtime.h>
#include <cstdint>

#define LSEQ 4096
#define DIM 768
#define HID 384
#define G4 1536
#define EN_ 32768
#define PN_ 32768
#define K3 2304   // 3*768 folded-K for pair MLP

// ---------------- scratch (device globals; no allocation allowed) ----------------
__device__ float g_xg[2][LSEQ][G4];
__device__ float g_tok[LSEQ][2 * HID];
__device__ float g_prefix[LSEQ + 1][2 * HID];
__device__ float g_csum[32][2 * HID];
__device__ float g_evemb[EN_][2 * HID];
__device__ float g_wp[DIM][K3];
__device__ float g_feat[PN_][K3];
__device__ float g_h1[PN_][DIM];
__device__ float g_h2[PN_][256];
__device__ unsigned long long g_hpack[2][2][HID];  // [dir][parity][hidx]: (tag<<32)|f32
__device__ int g_is64[3];

// ---------------- helpers ----------------
__device__ __forceinline__ long long fetch_idx(const void* p, int which, long long i) {
    if (g_is64[which]) return ((const long long*)p)[i];
    return (long long)((const int*)p)[i];
}
__device__ __forceinline__ float sigf(float x) { return 1.f / (1.f + __expf(-x)); }
__device__ __forceinline__ float tanh_fast(float x) {
    x = fminf(15.f, fmaxf(-15.f, x));
    float e = __expf(-2.f * x);
    return (1.f - e) / (1.f + e);
}
// volatile = morally strong -> single-copy atomic 64-bit (tag+data cannot tear)
__device__ __forceinline__ unsigned long long ldvol64(const unsigned long long* p) {
    unsigned long long v;
    asm volatile("ld.volatile.global.b64 %0, [%1];" : "=l"(v) : "l"(p));
    return v;
}
__device__ __forceinline__ void stvol64(unsigned long long* p, unsigned long long v) {
    asm volatile("st.volatile.global.b64 [%0], %1;" :: "l"(p), "l"(v));
}
__device__ __forceinline__ unsigned f2tf32(float f) {
    unsigned r;
    asm("cvt.rna.tf32.f32 %0, %1;" : "=r"(r) : "f"(f));
    return r;
}

// ---------------- dtype detection + init ----------------
__global__ void detect_kernel(const void* lab_ev, const void* pairs, const void* labt) {
    if (threadIdx.x == 0) {
        const int* a = (const int*)lab_ev;
        int nz = 0;
        for (int i = 0; i < 64; i++) nz |= a[2 * i + 1];
        g_is64[0] = (nz == 0);
        const int* b = (const int*)pairs;
        nz = 0;
        for (int i = 0; i < 64; i++) nz |= b[2 * i + 1];
        g_is64[1] = (nz == 0);
        const int* c = (const int*)labt;
        nz = 0;
        for (int i = 0; i < 64; i++) nz |= c[2 * i + 1];
        g_is64[2] = (nz == 0);
    }
}

__global__ void init_kernel(float* out, int loss_off) {
    int i = blockIdx.x * blockDim.x + threadIdx.x;
    if (i < 2 * 2 * HID) ((unsigned long long*)g_hpack)[i] = 0ULL;
    if (i == 0 && loss_off) out[0] = 0.f;
}

// ---------------- fp32 SIMT GEMM (xgate; exact) ----------------
#define BM 128
#define BN 128
#define BKG 16
__global__ void __launch_bounds__(256) sgemm_nt(const float* __restrict__ A,
                                                const float* __restrict__ B,
                                                float* __restrict__ C,
                                                int M, int N, int K,
                                                const float* __restrict__ bias, int relu) {
    __shared__ float As[BKG][BM];
    __shared__ float Bs[BKG][BN];
    int bm = blockIdx.y, bn = blockIdx.x;
    int tid = threadIdx.x;
    int tx = tid & 15, ty = tid >> 4;
    const float* Ab = A + (long long)bm * BM * K;
    const float* Bb = B + (long long)bn * BN * K;

    float acc[8][8];
#pragma unroll
    for (int i = 0; i < 8; i++)
#pragma unroll
        for (int j = 0; j < 8; j++) acc[i][j] = 0.f;

    float4 pa[2], pb[2];
#pragma unroll
    for (int b = 0; b < 2; b++) {
        int f = tid + b * 256;
        int row = f >> 2, c4 = f & 3;
        pa[b] = *(const float4*)(Ab + (long long)row * K + c4 * 4);
        pb[b] = *(const float4*)(Bb + (long long)row * K + c4 * 4);
    }

    for (int k0 = 0; k0 < K; k0 += BKG) {
#pragma unroll
        for (int b = 0; b < 2; b++) {
            int f = tid + b * 256;
            int row = f >> 2, c4 = f & 3;
            As[c4 * 4 + 0][row] = pa[b].x;
            As[c4 * 4 + 1][row] = pa[b].y;
            As[c4 * 4 + 2][row] = pa[b].z;
            As[c4 * 4 + 3][row] = pa[b].w;
            Bs[c4 * 4 + 0][row] = pb[b].x;
            Bs[c4 * 4 + 1][row] = pb[b].y;
            Bs[c4 * 4 + 2][row] = pb[b].z;
            Bs[c4 * 4 + 3][row] = pb[b].w;
        }
        __syncthreads();
        if (k0 + BKG < K) {
#pragma unroll
            for (int b = 0; b < 2; b++) {
                int f = tid + b * 256;
                int row = f >> 2, c4 = f & 3;
                pa[b] = *(const float4*)(Ab + (long long)row * K + (k0 + BKG) + c4 * 4);
                pb[b] = *(const float4*)(Bb + (long long)row * K + (k0 + BKG) + c4 * 4);
            }
        }
#pragma unroll
        for (int kk = 0; kk < BKG; kk++) {
            float a[8], bq[8];
            *(float4*)&a[0] = *(const float4*)&As[kk][ty * 8];
            *(float4*)&a[4] = *(const float4*)&As[kk][ty * 8 + 4];
            *(float4*)&bq[0] = *(const float4*)&Bs[kk][tx * 8];
            *(float4*)&bq[4] = *(const float4*)&Bs[kk][tx * 8 + 4];
#pragma unroll
            for (int i = 0; i < 8; i++)
#pragma unroll
                for (int j = 0; j < 8; j++) acc[i][j] += a[i] * bq[j];
        }
        __syncthreads();
    }

#pragma unroll
    for (int i = 0; i < 8; i++) {
        long long m = (long long)bm * BM + ty * 8 + i;
#pragma unroll
        for (int j = 0; j < 8; j += 4) {
            int n = bn * BN + tx * 8 + j;
            float4 v;
            v.x = acc[i][j + 0];
            v.y = acc[i][j + 1];
            v.z = acc[i][j + 2];
            v.w = acc[i][j + 3];
            if (bias) {
                v.x += bias[n + 0];
                v.y += bias[n + 1];
                v.z += bias[n + 2];
                v.w += bias[n + 3];
            }
            if (relu) {
                v.x = fmaxf(v.x, 0.f);
                v.y = fmaxf(v.y, 0.f);
                v.z = fmaxf(v.z, 0.f);
                v.w = fmaxf(v.w, 0.f);
            }
            *(float4*)(C + m * N + n) = v;
        }
    }
}

// ---------------- tf32 tensor-core GEMM (round-2 known-good layout) ----------------
#define TPAD 36
__global__ void __launch_bounds__(256) tgemm_nt(const float* __restrict__ A,
                                                const float* __restrict__ B,
                                                float* __restrict__ C,
                                                int M, int N, int K,
                                                const float* __restrict__ bias, int relu) {
    __shared__ unsigned As[128 * TPAD];
    __shared__ unsigned Bs[128 * TPAD];
    int bm = blockIdx.y, bn = blockIdx.x;
    int tid = threadIdx.x;
    int wid = tid >> 5, l = tid & 31;
    int wm = wid & 3, wn = wid >> 2;
    int gr = l >> 2, gc = l & 3;
    const float* Ab = A + (long long)bm * 128 * K;
    const float* Bb = B + (long long)bn * 128 * K;

    float acc[2][8][4];
#pragma unroll
    for (int mi = 0; mi < 2; mi++)
#pragma unroll
        for (int ni = 0; ni < 8; ni++)
#pragma unroll
            for (int c = 0; c < 4; c++) acc[mi][ni][c] = 0.f;

    int row[4], qk[4];
    float4 ra[4], rb[4];
#pragma unroll
    for (int i = 0; i < 4; i++) {
        int idx = tid + i * 256;
        row[i] = idx >> 3;
        qk[i] = idx & 7;
        ra[i] = *(const float4*)(Ab + (long long)row[i] * K + qk[i] * 4);
        rb[i] = *(const float4*)(Bb + (long long)row[i] * K + qk[i] * 4);
    }

    for (int k0 = 0; k0 < K; k0 += 32) {
#pragma unroll
        for (int i = 0; i < 4; i++) {
            int base = row[i] * TPAD + qk[i] * 4;
            As[base + 0] = f2tf32(ra[i].x);
            As[base + 1] = f2tf32(ra[i].y);
            As[base + 2] = f2tf32(ra[i].z);
            As[base + 3] = f2tf32(ra[i].w);
            Bs[base + 0] = f2tf32(rb[i].x);
            Bs[base + 1] = f2tf32(rb[i].y);
            Bs[base + 2] = f2tf32(rb[i].z);
            Bs[base + 3] = f2tf32(rb[i].w);
        }
        __syncthreads();
        if (k0 + 32 < K) {
#pragma unroll
            for (int i = 0; i < 4; i++) {
                ra[i] = *(const float4*)(Ab + (long long)row[i] * K + (k0 + 32) + qk[i] * 4);
                rb[i] = *(const float4*)(Bb + (long long)row[i] * K + (k0 + 32) + qk[i] * 4);
            }
        }
#pragma unroll
        for (int ks = 0; ks < 4; ks++) {
            unsigned a[2][4];
#pragma unroll
            for (int mi = 0; mi < 2; mi++) {
                int baseA = (wm * 32 + mi * 16 + gr) * TPAD + ks * 8 + gc;
                a[mi][0] = As[baseA];
                a[mi][1] = As[baseA + 8 * TPAD];
                a[mi][2] = As[baseA + 4];
                a[mi][3] = As[baseA + 8 * TPAD + 4];
            }
#pragma unroll
            for (int ni = 0; ni < 8; ni++) {
                int baseB = (wn * 64 + ni * 8 + gr) * TPAD + ks * 8 + gc;
                unsigned b0 = Bs[baseB];
                unsigned b1 = Bs[baseB + 4];
#pragma unroll
                for (int mi = 0; mi < 2; mi++) {
                    asm volatile(
                        "mma.sync.aligned.m16n8k8.row.col.f32.tf32.tf32.f32 "
                        "{%0,%1,%2,%3}, {%4,%5,%6,%7}, {%8,%9}, {%0,%1,%2,%3};\n"
                        : "+f"(acc[mi][ni][0]), "+f"(acc[mi][ni][1]),
                          "+f"(acc[mi][ni][2]), "+f"(acc[mi][ni][3])
                        : "r"(a[mi][0]), "r"(a[mi][1]), "r"(a[mi][2]), "r"(a[mi][3]),
                          "r"(b0), "r"(b1));
                }
            }
        }
        __syncthreads();
    }

#pragma unroll
    for (int mi = 0; mi < 2; mi++) {
#pragma unroll
        for (int ni = 0; ni < 8; ni++) {
            int rowc = bm * 128 + wm * 32 + mi * 16 + gr;
            int colc = bn * 128 + wn * 64 + ni * 8 + 2 * gc;
            float b0v = bias ? bias[colc] : 0.f;
            float b1v = bias ? bias[colc + 1] : 0.f;
            float2 v0, v1;
            v0.x = acc[mi][ni][0] + b0v;
            v0.y = acc[mi][ni][1] + b1v;
            v1.x = acc[mi][ni][2] + b0v;
            v1.y = acc[mi][ni][3] + b1v;
            if (relu) {
                v0.x = fmaxf(v0.x, 0.f);
                v0.y = fmaxf(v0.y, 0.f);
                v1.x = fmaxf(v1.x, 0.f);
                v1.y = fmaxf(v1.y, 0.f);
            }
            *(float2*)(C + (long long)rowc * N + colc) = v0;
            *(float2*)(C + (long long)(rowc + 8) * N + colc) = v1;
        }
    }
}

// ---------------- LSTM: interleaved dual-direction, exchange hidden behind compute ----
// 64 CTAs; CTA cid owns h rows [cid*6, cid*6+6) for BOTH directions.
// Warp w owns local gate rows q = w*3+{0,1,2}; q = gate*6 + r.
// Phases per iteration t:  A: fwd compute+post  B: gather bwd(t)
//                          C: bwd compute+post  D: gather fwd(t+1)
#define MATVEC(d, xv)                                                      \
    {                                                                      \
        float hk[12];                                                      \
        _Pragma("unroll")                                                  \
        for (int k = 0; k < 12; k++) hk[k] = h_sh[d][l + 32 * k];          \
        float a0 = 0.f, a1 = 0.f, a2 = 0.f;                                \
        _Pragma("unroll")                                                  \
        for (int k = 0; k < 12; k++) {                                     \
            float hh = hk[k];                                              \
            a0 += W[d][0][k] * hh;                                         \
            a1 += W[d][1][k] * hh;                                         \
            a2 += W[d][2][k] * hh;                                         \
        }                                                                  \
        _Pragma("unroll")                                                  \
        for (int st = 16; st > 0; st >>= 1) {                              \
            a0 += __shfl_xor_sync(0xffffffffu, a0, st);                    \
            a1 += __shfl_xor_sync(0xffffffffu, a1, st);                    \
            a2 += __shfl_xor_sync(0xffffffffu, a2, st);                    \
        }                                                                  \
        if (l < 3) {                                                       \
            float my = (l == 0) ? a0 : (l == 1) ? a1 : a2;                 \
            gate_sh[d][w * 3 + l] = my + (xv) + mybias[d];                 \
        }                                                                  \
    }

#define ACT_POST(d, cvar, trow)                                            \
    if (tid < 6) {                                                         \
        float iv = sigf(gate_sh[d][tid]);                                  \
        float fv = sigf(gate_sh[d][6 + tid]);                              \
        float gv = tanh_fast(gate_sh[d][12 + tid]);                        \
        float ov = sigf(gate_sh[d][18 + tid]);                             \
        cvar = fv * cvar + iv * gv;                                        \
        float hv = ov * tanh_fast(cvar);                                   \
        int hidx = cid * 6 + tid;                                          \
        stvol64(&g_hpack[d][parn][hidx],                                   \
                ((unsigned long long)tagn << 32) |                         \
                (unsigned)__float_as_int(hv));                             \
        g_tok[trow][(d)*HID + hidx] = hv;                                  \
    }

#define GATHER(d, parx, tagx)                                              \
    {                                                                      \
        const unsigned long long* hp = &g_hpack[d][parx][0];               \
        unsigned long long v1 = ldvol64(hp + tid);                         \
        unsigned long long v2 = 0ULL;                                      \
        if (tid < 128) v2 = ldvol64(hp + tid + 256);                       \
        while ((unsigned)(v1 >> 32) != (unsigned)(tagx))                   \
            v1 = ldvol64(hp + tid);                                        \
        h_sh[d][tid] = __int_as_float((int)(unsigned)v1);                  \
        if (tid < 128) {                                                   \
            while ((unsigned)(v2 >> 32) != (unsigned)(tagx))               \
                v2 = ldvol64(hp + tid + 256);                              \
            h_sh[d][tid + 256] = __int_as_float((int)(unsigned)v2);        \
        }                                                                  \
    }

__global__ void __launch_bounds__(256, 1) lstm_kernel(const float* __restrict__ w_hh_f,
                                                      const float* __restrict__ b_f,
                                                      const float* __restrict__ w_hh_b,
                                                      const float* __restrict__ b_b) {
    int cid = blockIdx.x;   // 0..63
    int tid = threadIdx.x;
    int w = tid >> 5, l = tid & 31;

    __shared__ float h_sh[2][HID];
    __shared__ float gate_sh[2][24];

    const float* whh[2] = {w_hh_f, w_hh_b};
    const float* bbp[2] = {b_f, b_b};

    // register-resident w_hh slices, both dirs
    float W[2][3][12];
#pragma unroll
    for (int i = 0; i < 3; i++) {
        int q = w * 3 + i;
        int grow = (q / 6) * HID + cid * 6 + (q % 6);
#pragma unroll
        for (int k = 0; k < 12; k++) {
            W[0][i][k] = whh[0][(long long)grow * HID + (l + 32 * k)];
            W[1][i][k] = whh[1][(long long)grow * HID + (l + 32 * k)];
        }
    }
    int myrow = 0;
    float mybias[2] = {0.f, 0.f};
    if (l < 3) {
        int q = w * 3 + l;
        myrow = (q / 6) * HID + cid * 6 + (q % 6);
        mybias[0] = bbp[0][myrow];
        mybias[1] = bbp[1][myrow];
    }
    const float* xg0 = &g_xg[0][0][0];
    const float* xg1 = &g_xg[1][0][0];

    float c0 = 0.f, c1 = 0.f;
    for (int i = tid; i < 2 * HID; i += 256) ((float*)h_sh)[i] = 0.f;
    __syncthreads();

    float xv0 = 0.f, xv1 = 0.f;
    if (l < 3) {
        xv0 = __ldg(xg0 + myrow);                                  // fwd t=0
        xv1 = __ldg(xg1 + (long long)(LSEQ - 1) * G4 + myrow);     // bwd t=0
    }

    for (int t = 0; t < LSEQ; t++) {
        // prefetch x for iteration t+1 (hidden behind the whole iteration)
        float xn0 = 0.f, xn1 = 0.f;
        if (l < 3 && t + 1 < LSEQ) {
            xn0 = __ldg(xg0 + (long long)(t + 1) * G4 + myrow);
            xn1 = __ldg(xg1 + (long long)(LSEQ - 2 - t) * G4 + myrow);
        }
        int par = t & 1;
        int parn = (t + 1) & 1;
        unsigned tagn = (unsigned)(t + 1);

        // A: fwd compute + post h_f(t+1)
        MATVEC(0, xv0)
        __syncthreads();
        ACT_POST(0, c0, t)

        // B: gather h_b(t) (posted one D+A phase ago)
        GATHER(1, par, t)
        __syncthreads();

        // C: bwd compute + post h_b(t+1)
        MATVEC(1, xv1)
        __syncthreads();
        ACT_POST(1, c1, LSEQ - 1 - t)

        // D: gather h_f(t+1) (posted one B+C phase ago)
        GATHER(0, parn, tagn)
        __syncthreads();

        xv0 = xn0;
        xv1 = xn1;
    }
}

// ---------------- 3-phase parallel scan over tok ----------------
__global__ void scan1_kernel() {
    int b = blockIdx.x;
    for (int d = threadIdx.x; d < 2 * HID; d += 256) {
        float s = 0.f;
        for (int r = 0; r < 128; r++) s += g_tok[b * 128 + r][d];
        g_csum[b][d] = s;
    }
}
__global__ void scan2_kernel() {
    int d = threadIdx.x;
    float run = 0.f;
    for (int b = 0; b < 32; b++) {
        float v = g_csum[b][d];
        g_csum[b][d] = run;
        run += v;
    }
}
__global__ void scan3_kernel() {
    int b = blockIdx.x;
    for (int d = threadIdx.x; d < 2 * HID; d += 256) {
        float run = g_csum[b][d];
        if (b == 0) g_prefix[0][d] = 0.f;
        for (int r = 0; r < 128; r++) {
            run += g_tok[b * 128 + r][d];
            g_prefix[b * 128 + r + 1][d] = run;
        }
    }
}

// ---------------- event embeddings ----------------
__global__ void event_kernel(const void* __restrict__ lab_ev) {
    int d = blockIdx.x * blockDim.x + threadIdx.x;
    int e = blockIdx.y;
    if (d >= 2 * HID) return;
    long long st = fetch_idx(lab_ev, 0, 2LL * e);
    long long en = fetch_idx(lab_ev, 0, 2LL * e + 1);
    g_evemb[e][d] = (g_prefix[en][d] - g_prefix[st][d]) / (float)(en - st);
}

// ---------------- fold W1 into [A|B|C] ----------------
__global__ void wprep_kernel(const float* __restrict__ w1) {
    int k = blockIdx.x * blockDim.x + threadIdx.x;
    int n = blockIdx.y;
    if (k >= K3) return;
    int seg = k / 768, kk = k - seg * 768;
    const float* r = w1 + (long long)n * 3072;
    float v;
    if (seg == 0) v = r[kk] + r[1536 + kk];
    else if (seg == 1) v = r[768 + kk] - r[1536 + kk];
    else v = r[2304 + kk];
    g_wp[n][k] = v;
}

// ---------------- folded feature build: [e1 | e2 | e1*e2] ----------------
__global__ void feat_kernel(const void* __restrict__ pairs) {
    int k = blockIdx.x * blockDim.x + threadIdx.x;
    int p = blockIdx.y;
    if (k >= K3) return;
    int seg = k / 768, kk = k - seg * 768;
    long long i1 = fetch_idx(pairs, 1, 2LL * p);
    long long i2 = fetch_idx(pairs, 1, 2LL * p + 1);
    float v;
    if (seg == 0) v = g_evemb[i1][kk];
    else if (seg == 1) v = g_evemb[i2][kk];
    else v = g_evemb[i1][kk] * g_evemb[i2][kk];
    g_feat[p][k] = v;
}

// ---------------- scores + log-softmax + CE + loss ----------------
__global__ void scores_kernel(const float* __restrict__ w3, const float* __restrict__ b3,
                              const void* __restrict__ labt, float* __restrict__ out,
                              int loss_off) {
    __shared__ float w3s[4][256];
    __shared__ float ce_sh[8];
    int tid = threadIdx.x;
    int wp = tid >> 5, l = tid & 31;
    for (int i = tid; i < 1024; i += 256) w3s[i >> 8][i & 255] = w3[i];
    __syncthreads();

    int p = blockIdx.x * 8 + wp;
    const float* h2r = &g_h2[p][0];
    float hv[8];
#pragma unroll
    for (int k = 0; k < 8; k++) hv[k] = h2r[l + 32 * k];
    float s[4];
#pragma unroll
    for (int j = 0; j < 4; j++) {
        float t = 0.f;
#pragma unroll
        for (int k = 0; k < 8; k++) t += hv[k] * w3s[j][l + 32 * k];
        t += __shfl_xor_sync(0xffffffffu, t, 16);
        t += __shfl_xor_sync(0xffffffffu, t, 8);
        t += __shfl_xor_sync(0xffffffffu, t, 4);
        t += __shfl_xor_sync(0xffffffffu, t, 2);
        t += __shfl_xor_sync(0xffffffffu, t, 1);
        s[j] = t + b3[j];
    }
    if (l == 0) {
        float m = fmaxf(fmaxf(s[0], s[1]), fmaxf(s[2], s[3]));
        float se = expf(s[0] - m) + expf(s[1] - m) + expf(s[2] - m) + expf(s[3] - m);
        float lse = m + logf(se);
        long long y = fetch_idx(labt, 2, p);
        float sy = (y == 0) ? s[0] : (y == 1) ? s[1] : (y == 2) ? s[2] : s[3];
        float* o = out + loss_off + 4LL * p;
        o[0] = s[0]; o[1] = s[1]; o[2] = s[2]; o[3] = s[3];
        ce_sh[wp] = lse - sy;
    }
    __syncthreads();
    if (tid == 0 && loss_off) {
        float t = 0.f;
#pragma unroll
        for (int i = 0; i < 8; i++) t += ce_sh[i];
        atomicAdd(out, t);
    }
}

// ---------------- launch ----------------
extern "C" void kernel_launch(void* const* d_in, const int* in_sizes, int n_in,
                              void* d_out, int out_size) {
    const float* tokemb = (const float*)d_in[0];
    const float* w_ih_f = (const float*)d_in[1];
    const float* w_hh_f = (const float*)d_in[2];
    const float* b_f = (const float*)d_in[3];
    const float* w_ih_b = (const float*)d_in[4];
    const float* w_hh_b = (const float*)d_in[5];
    const float* b_b = (const float*)d_in[6];
    const float* w1 = (const float*)d_in[7];
    const float* b1 = (const float*)d_in[8];
    const float* w2 = (const float*)d_in[9];
    const float* b2 = (const float*)d_in[10];
    const float* w3 = (const float*)d_in[11];
    const float* b3 = (const float*)d_in[12];
    const void* lab_ev = d_in[13];
    const void* pairs = d_in[14];
    const void* labt = d_in[15];
    float* out = (float*)d_out;
    int loss_off = (out_size > 4 * PN_) ? 1 : 0;

    void *p_xg, *p_wp, *p_feat, *p_h1, *p_h2;
    cudaGetSymbolAddress(&p_xg, g_xg);
    cudaGetSymbolAddress(&p_wp, g_wp);
    cudaGetSymbolAddress(&p_feat, g_feat);
    cudaGetSymbolAddress(&p_h1, g_h1);
    cudaGetSymbolAddress(&p_h2, g_h2);
    float* xg0 = (float*)p_xg;
    float* xg1 = xg0 + (long long)LSEQ * G4;

    detect_kernel<<<1, 1>>>(lab_ev, pairs, labt);
    init_kernel<<<32, 256>>>(out, loss_off);

    // input-side gate preactivations (fp32, exact — feeds the recurrence)
    sgemm_nt<<<dim3(G4 / BN, LSEQ / BM), 256>>>(tokemb, w_ih_f, xg0, LSEQ, G4, DIM, nullptr, 0);
    sgemm_nt<<<dim3(G4 / BN, LSEQ / BM), 256>>>(tokemb, w_ih_b, xg1, LSEQ, G4, DIM, nullptr, 0);

    // recurrence: 64 CTAs, both directions interleaved per CTA
    lstm_kernel<<<64, 256>>>(w_hh_f, b_f, w_hh_b, b_b);

    // 3-phase prefix scan + event embeddings
    scan1_kernel<<<32, 256>>>();
    scan2_kernel<<<1, 2 * HID>>>();
    scan3_kernel<<<32, 256>>>();
    event_kernel<<<dim3(3, EN_), 256>>>(lab_ev);

    // folded pair MLP (tf32 tensor cores)
    wprep_kernel<<<dim3(9, DIM), 256>>>(w1);
    feat_kernel<<<dim3(9, PN_), 256>>>(pairs);
    tgemm_nt<<<dim3(DIM / 128, PN_ / 128), 256>>>((const float*)p_feat, (const float*)p_wp,
                                                  (float*)p_h1, PN_, DIM, K3, b1, 1);
    tgemm_nt<<<dim3(256 / 128, PN_ / 128), 256>>>((const float*)p_h1, w2, (float*)p_h2,
                                                  PN_, 256, DIM, b2, 1);

    // scores + loss
    scores_kernel<<<PN_ / 8, 256>>>(w3, b3, labt, out, loss_off);
}

// round 6
// speedup vs baseline: 1.3962x; 1.3962x over previous
#include <cuda_runtime.h>
#include <cstdint>

#define LSEQ 4096
#define DIM 768
#define HID 384
#define G4 1536
#define EN_ 32768
#define PN_ 32768
#define K3 2304   // 3*768 folded-K for pair MLP

// ---------------- scratch (device globals; no allocation allowed) ----------------
__device__ float g_xg[2][LSEQ][G4];
__device__ float g_tok[LSEQ][2 * HID];
__device__ float g_prefix[LSEQ + 1][2 * HID];
__device__ float g_csum[32][2 * HID];
__device__ float g_evemb[EN_][2 * HID];
__device__ float g_wp[DIM][K3];
__device__ float g_h1[PN_][DIM];
__device__ float g_h2[PN_][256];
__device__ unsigned long long g_hpack[2][2][HID];  // [dir][parity][hidx]: (tag<<32)|f32
__device__ int g_is64[3];

// ---------------- helpers ----------------
__device__ __forceinline__ long long fetch_idx(const void* p, int which, long long i) {
    if (g_is64[which]) return ((const long long*)p)[i];
    return (long long)((const int*)p)[i];
}
__device__ __forceinline__ float sigf(float x) { return 1.f / (1.f + __expf(-x)); }
__device__ __forceinline__ float tanh_fast(float x) {
    x = fminf(15.f, fmaxf(-15.f, x));
    float e = __expf(-2.f * x);
    return (1.f - e) / (1.f + e);
}
// volatile = morally strong -> single-copy atomic 64-bit (tag+data cannot tear)
__device__ __forceinline__ unsigned long long ldvol64(const unsigned long long* p) {
    unsigned long long v;
    asm volatile("ld.volatile.global.b64 %0, [%1];" : "=l"(v) : "l"(p));
    return v;
}
__device__ __forceinline__ void stvol64(unsigned long long* p, unsigned long long v) {
    asm volatile("st.volatile.global.b64 [%0], %1;" :: "l"(p), "l"(v));
}
__device__ __forceinline__ unsigned f2tf32(float f) {
    unsigned r;
    asm("cvt.rna.tf32.f32 %0, %1;" : "=r"(r) : "f"(f));
    return r;
}

// ---------------- dtype detection + init ----------------
__global__ void detect_kernel(const void* lab_ev, const void* pairs, const void* labt) {
    if (threadIdx.x == 0) {
        const int* a = (const int*)lab_ev;
        int nz = 0;
        for (int i = 0; i < 64; i++) nz |= a[2 * i + 1];
        g_is64[0] = (nz == 0);
        const int* b = (const int*)pairs;
        nz = 0;
        for (int i = 0; i < 64; i++) nz |= b[2 * i + 1];
        g_is64[1] = (nz == 0);
        const int* c = (const int*)labt;
        nz = 0;
        for (int i = 0; i < 64; i++) nz |= c[2 * i + 1];
        g_is64[2] = (nz == 0);
    }
}

__global__ void init_kernel(float* out, int loss_off) {
    int i = blockIdx.x * blockDim.x + threadIdx.x;
    if (i < 2 * 2 * HID) ((unsigned long long*)g_hpack)[i] = 0ULL;
    if (i == 0 && loss_off) out[0] = 0.f;
}

// ---------------- fp32 SIMT GEMM (xgate; exact) ----------------
#define BM 128
#define BN 128
#define BKG 16
__global__ void __launch_bounds__(256) sgemm_nt(const float* __restrict__ A,
                                                const float* __restrict__ B,
                                                float* __restrict__ C,
                                                int M, int N, int K,
                                                const float* __restrict__ bias, int relu) {
    __shared__ float As[BKG][BM];
    __shared__ float Bs[BKG][BN];
    int bm = blockIdx.y, bn = blockIdx.x;
    int tid = threadIdx.x;
    int tx = tid & 15, ty = tid >> 4;
    const float* Ab = A + (long long)bm * BM * K;
    const float* Bb = B + (long long)bn * BN * K;

    float acc[8][8];
#pragma unroll
    for (int i = 0; i < 8; i++)
#pragma unroll
        for (int j = 0; j < 8; j++) acc[i][j] = 0.f;

    float4 pa[2], pb[2];
#pragma unroll
    for (int b = 0; b < 2; b++) {
        int f = tid + b * 256;
        int row = f >> 2, c4 = f & 3;
        pa[b] = *(const float4*)(Ab + (long long)row * K + c4 * 4);
        pb[b] = *(const float4*)(Bb + (long long)row * K + c4 * 4);
    }

    for (int k0 = 0; k0 < K; k0 += BKG) {
#pragma unroll
        for (int b = 0; b < 2; b++) {
            int f = tid + b * 256;
            int row = f >> 2, c4 = f & 3;
            As[c4 * 4 + 0][row] = pa[b].x;
            As[c4 * 4 + 1][row] = pa[b].y;
            As[c4 * 4 + 2][row] = pa[b].z;
            As[c4 * 4 + 3][row] = pa[b].w;
            Bs[c4 * 4 + 0][row] = pb[b].x;
            Bs[c4 * 4 + 1][row] = pb[b].y;
            Bs[c4 * 4 + 2][row] = pb[b].z;
            Bs[c4 * 4 + 3][row] = pb[b].w;
        }
        __syncthreads();
        if (k0 + BKG < K) {
#pragma unroll
            for (int b = 0; b < 2; b++) {
                int f = tid + b * 256;
                int row = f >> 2, c4 = f & 3;
                pa[b] = *(const float4*)(Ab + (long long)row * K + (k0 + BKG) + c4 * 4);
                pb[b] = *(const float4*)(Bb + (long long)row * K + (k0 + BKG) + c4 * 4);
            }
        }
#pragma unroll
        for (int kk = 0; kk < BKG; kk++) {
            float a[8], bq[8];
            *(float4*)&a[0] = *(const float4*)&As[kk][ty * 8];
            *(float4*)&a[4] = *(const float4*)&As[kk][ty * 8 + 4];
            *(float4*)&bq[0] = *(const float4*)&Bs[kk][tx * 8];
            *(float4*)&bq[4] = *(const float4*)&Bs[kk][tx * 8 + 4];
#pragma unroll
            for (int i = 0; i < 8; i++)
#pragma unroll
                for (int j = 0; j < 8; j++) acc[i][j] += a[i] * bq[j];
        }
        __syncthreads();
    }

#pragma unroll
    for (int i = 0; i < 8; i++) {
        long long m = (long long)bm * BM + ty * 8 + i;
#pragma unroll
        for (int j = 0; j < 8; j += 4) {
            int n = bn * BN + tx * 8 + j;
            float4 v;
            v.x = acc[i][j + 0];
            v.y = acc[i][j + 1];
            v.z = acc[i][j + 2];
            v.w = acc[i][j + 3];
            if (bias) {
                v.x += bias[n + 0];
                v.y += bias[n + 1];
                v.z += bias[n + 2];
                v.w += bias[n + 3];
            }
            if (relu) {
                v.x = fmaxf(v.x, 0.f);
                v.y = fmaxf(v.y, 0.f);
                v.z = fmaxf(v.z, 0.f);
                v.w = fmaxf(v.w, 0.f);
            }
            *(float4*)(C + m * N + n) = v;
        }
    }
}

// ---------------- tf32 tensor-core GEMM (round-2 known-good layout) ----------------
#define TPAD 36
__global__ void __launch_bounds__(256) tgemm_nt(const float* __restrict__ A,
                                                const float* __restrict__ B,
                                                float* __restrict__ C,
                                                int M, int N, int K,
                                                const float* __restrict__ bias, int relu) {
    __shared__ unsigned As[128 * TPAD];
    __shared__ unsigned Bs[128 * TPAD];
    int bm = blockIdx.y, bn = blockIdx.x;
    int tid = threadIdx.x;
    int wid = tid >> 5, l = tid & 31;
    int wm = wid & 3, wn = wid >> 2;
    int gr = l >> 2, gc = l & 3;
    const float* Ab = A + (long long)bm * 128 * K;
    const float* Bb = B + (long long)bn * 128 * K;

    float acc[2][8][4];
#pragma unroll
    for (int mi = 0; mi < 2; mi++)
#pragma unroll
        for (int ni = 0; ni < 8; ni++)
#pragma unroll
            for (int c = 0; c < 4; c++) acc[mi][ni][c] = 0.f;

    int row[4], qk[4];
    float4 ra[4], rb[4];
#pragma unroll
    for (int i = 0; i < 4; i++) {
        int idx = tid + i * 256;
        row[i] = idx >> 3;
        qk[i] = idx & 7;
        ra[i] = *(const float4*)(Ab + (long long)row[i] * K + qk[i] * 4);
        rb[i] = *(const float4*)(Bb + (long long)row[i] * K + qk[i] * 4);
    }

    for (int k0 = 0; k0 < K; k0 += 32) {
#pragma unroll
        for (int i = 0; i < 4; i++) {
            int base = row[i] * TPAD + qk[i] * 4;
            As[base + 0] = f2tf32(ra[i].x);
            As[base + 1] = f2tf32(ra[i].y);
            As[base + 2] = f2tf32(ra[i].z);
            As[base + 3] = f2tf32(ra[i].w);
            Bs[base + 0] = f2tf32(rb[i].x);
            Bs[base + 1] = f2tf32(rb[i].y);
            Bs[base + 2] = f2tf32(rb[i].z);
            Bs[base + 3] = f2tf32(rb[i].w);
        }
        __syncthreads();
        if (k0 + 32 < K) {
#pragma unroll
            for (int i = 0; i < 4; i++) {
                ra[i] = *(const float4*)(Ab + (long long)row[i] * K + (k0 + 32) + qk[i] * 4);
                rb[i] = *(const float4*)(Bb + (long long)row[i] * K + (k0 + 32) + qk[i] * 4);
            }
        }
#pragma unroll
        for (int ks = 0; ks < 4; ks++) {
            unsigned a[2][4];
#pragma unroll
            for (int mi = 0; mi < 2; mi++) {
                int baseA = (wm * 32 + mi * 16 + gr) * TPAD + ks * 8 + gc;
                a[mi][0] = As[baseA];
                a[mi][1] = As[baseA + 8 * TPAD];
                a[mi][2] = As[baseA + 4];
                a[mi][3] = As[baseA + 8 * TPAD + 4];
            }
#pragma unroll
            for (int ni = 0; ni < 8; ni++) {
                int baseB = (wn * 64 + ni * 8 + gr) * TPAD + ks * 8 + gc;
                unsigned b0 = Bs[baseB];
                unsigned b1 = Bs[baseB + 4];
#pragma unroll
                for (int mi = 0; mi < 2; mi++) {
                    asm volatile(
                        "mma.sync.aligned.m16n8k8.row.col.f32.tf32.tf32.f32 "
                        "{%0,%1,%2,%3}, {%4,%5,%6,%7}, {%8,%9}, {%0,%1,%2,%3};\n"
                        : "+f"(acc[mi][ni][0]), "+f"(acc[mi][ni][1]),
                          "+f"(acc[mi][ni][2]), "+f"(acc[mi][ni][3])
                        : "r"(a[mi][0]), "r"(a[mi][1]), "r"(a[mi][2]), "r"(a[mi][3]),
                          "r"(b0), "r"(b1));
                }
            }
        }
        __syncthreads();
    }

#pragma unroll
    for (int mi = 0; mi < 2; mi++) {
#pragma unroll
        for (int ni = 0; ni < 8; ni++) {
            int rowc = bm * 128 + wm * 32 + mi * 16 + gr;
            int colc = bn * 128 + wn * 64 + ni * 8 + 2 * gc;
            float b0v = bias ? bias[colc] : 0.f;
            float b1v = bias ? bias[colc + 1] : 0.f;
            float2 v0, v1;
            v0.x = acc[mi][ni][0] + b0v;
            v0.y = acc[mi][ni][1] + b1v;
            v1.x = acc[mi][ni][2] + b0v;
            v1.y = acc[mi][ni][3] + b1v;
            if (relu) {
                v0.x = fmaxf(v0.x, 0.f);
                v0.y = fmaxf(v0.y, 0.f);
                v1.x = fmaxf(v1.x, 0.f);
                v1.y = fmaxf(v1.y, 0.f);
            }
            *(float2*)(C + (long long)rowc * N + colc) = v0;
            *(float2*)(C + (long long)(rowc + 8) * N + colc) = v1;
        }
    }
}

// ---------------- fused feat+GEMM1: A[p][k] gathered from evemb on the fly ----------
// A row p: [e1 | e2 | e1*e2] with e1=evemb[pairs[p].x], e2=evemb[pairs[p].y].
// B = g_wp (folded W1). M=PN_, K=K3.
__device__ __forceinline__ float4 feat_lda(const int2* pr_sh, int lrow, int k) {
    int seg = k / 768, kk = k - seg * 768;
    int2 pr = pr_sh[lrow];
    if (seg == 0) return *(const float4*)&g_evemb[pr.x][kk];
    if (seg == 1) return *(const float4*)&g_evemb[pr.y][kk];
    float4 a = *(const float4*)&g_evemb[pr.x][kk];
    float4 b = *(const float4*)&g_evemb[pr.y][kk];
    return make_float4(a.x * b.x, a.y * b.y, a.z * b.z, a.w * b.w);
}

__global__ void __launch_bounds__(256) tgemm_feat(const void* __restrict__ pairs,
                                                  float* __restrict__ C,
                                                  const float* __restrict__ bias) {
    const int N = DIM, K = K3;
    __shared__ unsigned As[128 * TPAD];
    __shared__ unsigned Bs[128 * TPAD];
    __shared__ int2 pr_sh[128];
    int bm = blockIdx.y, bn = blockIdx.x;
    int tid = threadIdx.x;
    int wid = tid >> 5, l = tid & 31;
    int wm = wid & 3, wn = wid >> 2;
    int gr = l >> 2, gc = l & 3;
    const float* Bb = &g_wp[bn * 128][0];

    if (tid < 128) {
        long long p = (long long)bm * 128 + tid;
        pr_sh[tid] = make_int2((int)fetch_idx(pairs, 1, 2 * p),
                               (int)fetch_idx(pairs, 1, 2 * p + 1));
    }
    __syncthreads();

    float acc[2][8][4];
#pragma unroll
    for (int mi = 0; mi < 2; mi++)
#pragma unroll
        for (int ni = 0; ni < 8; ni++)
#pragma unroll
            for (int c = 0; c < 4; c++) acc[mi][ni][c] = 0.f;

    int row[4], qk[4];
    float4 ra[4], rb[4];
#pragma unroll
    for (int i = 0; i < 4; i++) {
        int idx = tid + i * 256;
        row[i] = idx >> 3;
        qk[i] = idx & 7;
        ra[i] = feat_lda(pr_sh, row[i], qk[i] * 4);
        rb[i] = *(const float4*)(Bb + (long long)row[i] * K + qk[i] * 4);
    }

    for (int k0 = 0; k0 < K; k0 += 32) {
#pragma unroll
        for (int i = 0; i < 4; i++) {
            int base = row[i] * TPAD + qk[i] * 4;
            As[base + 0] = f2tf32(ra[i].x);
            As[base + 1] = f2tf32(ra[i].y);
            As[base + 2] = f2tf32(ra[i].z);
            As[base + 3] = f2tf32(ra[i].w);
            Bs[base + 0] = f2tf32(rb[i].x);
            Bs[base + 1] = f2tf32(rb[i].y);
            Bs[base + 2] = f2tf32(rb[i].z);
            Bs[base + 3] = f2tf32(rb[i].w);
        }
        __syncthreads();
        if (k0 + 32 < K) {
#pragma unroll
            for (int i = 0; i < 4; i++) {
                ra[i] = feat_lda(pr_sh, row[i], (k0 + 32) + qk[i] * 4);
                rb[i] = *(const float4*)(Bb + (long long)row[i] * K + (k0 + 32) + qk[i] * 4);
            }
        }
#pragma unroll
        for (int ks = 0; ks < 4; ks++) {
            unsigned a[2][4];
#pragma unroll
            for (int mi = 0; mi < 2; mi++) {
                int baseA = (wm * 32 + mi * 16 + gr) * TPAD + ks * 8 + gc;
                a[mi][0] = As[baseA];
                a[mi][1] = As[baseA + 8 * TPAD];
                a[mi][2] = As[baseA + 4];
                a[mi][3] = As[baseA + 8 * TPAD + 4];
            }
#pragma unroll
            for (int ni = 0; ni < 8; ni++) {
                int baseB = (wn * 64 + ni * 8 + gr) * TPAD + ks * 8 + gc;
                unsigned b0 = Bs[baseB];
                unsigned b1 = Bs[baseB + 4];
#pragma unroll
                for (int mi = 0; mi < 2; mi++) {
                    asm volatile(
                        "mma.sync.aligned.m16n8k8.row.col.f32.tf32.tf32.f32 "
                        "{%0,%1,%2,%3}, {%4,%5,%6,%7}, {%8,%9}, {%0,%1,%2,%3};\n"
                        : "+f"(acc[mi][ni][0]), "+f"(acc[mi][ni][1]),
                          "+f"(acc[mi][ni][2]), "+f"(acc[mi][ni][3])
                        : "r"(a[mi][0]), "r"(a[mi][1]), "r"(a[mi][2]), "r"(a[mi][3]),
                          "r"(b0), "r"(b1));
                }
            }
        }
        __syncthreads();
    }

#pragma unroll
    for (int mi = 0; mi < 2; mi++) {
#pragma unroll
        for (int ni = 0; ni < 8; ni++) {
            int rowc = bm * 128 + wm * 32 + mi * 16 + gr;
            int colc = bn * 128 + wn * 64 + ni * 8 + 2 * gc;
            float b0v = bias[colc];
            float b1v = bias[colc + 1];
            float2 v0, v1;
            v0.x = fmaxf(acc[mi][ni][0] + b0v, 0.f);
            v0.y = fmaxf(acc[mi][ni][1] + b1v, 0.f);
            v1.x = fmaxf(acc[mi][ni][2] + b0v, 0.f);
            v1.y = fmaxf(acc[mi][ni][3] + b1v, 0.f);
            *(float2*)(C + (long long)rowc * N + colc) = v0;
            *(float2*)(C + (long long)(rowc + 8) * N + colc) = v1;
        }
    }
}

// ---------------- LSTM recurrence: R4 structure + dual-issue gather ----------------
__global__ void __launch_bounds__(256, 1) lstm_kernel(const float* __restrict__ w_hh_f,
                                                      const float* __restrict__ b_f,
                                                      const float* __restrict__ w_hh_b,
                                                      const float* __restrict__ b_b) {
    int dir = blockIdx.x >> 5;
    int cid = blockIdx.x & 31;
    const float* whh = dir ? w_hh_b : w_hh_f;
    const float* bb = dir ? b_b : b_f;
    int tid = threadIdx.x;
    int w = tid >> 5, l = tid & 31;

    __shared__ float h_sh[HID];
    __shared__ float gate_sh[48];

    // register-resident w_hh slice: warp w owns 6 gate rows, lane l columns {l+32k}
    float W[6][12];
#pragma unroll
    for (int i = 0; i < 6; i++) {
        int q = w * 6 + i;
        int grow = (q / 12) * HID + cid * 12 + (q % 12);
#pragma unroll
        for (int k = 0; k < 12; k++) W[i][k] = whh[(long long)grow * HID + (l + 32 * k)];
    }
    int q_h = w * 6 + l;  // valid for l < 6
    int gx = (l < 6) ? ((q_h / 12) * HID + cid * 12 + (q_h % 12)) : 0;
    float bias_h = (l < 6) ? bb[gx] : 0.f;
    const float* xg = &g_xg[dir][0][0];

    float cstate = 0.f;
    for (int i = tid; i < HID; i += 256) h_sh[i] = 0.f;
    __syncthreads();

    int trow0 = dir ? (LSEQ - 1) : 0;
    float xval = (l < 6) ? __ldg(xg + (long long)trow0 * G4 + gx) : 0.f;

    for (int t = 0; t < LSEQ; t++) {
        int trow = dir ? (LSEQ - 1 - t) : t;
        float xnext = 0.f;
        if (l < 6 && t + 1 < LSEQ) {
            int trn = dir ? (LSEQ - 2 - t) : (t + 1);
            xnext = __ldg(xg + (long long)trn * G4 + gx);
        }

        // 6 dot products first (ILP), then interleaved butterfly stages
        float hk[12];
#pragma unroll
        for (int k = 0; k < 12; k++) hk[k] = h_sh[l + 32 * k];
        float a0 = 0.f, a1 = 0.f, a2 = 0.f, a3 = 0.f, a4 = 0.f, a5 = 0.f;
#pragma unroll
        for (int k = 0; k < 12; k++) {
            float h = hk[k];
            a0 += W[0][k] * h;
            a1 += W[1][k] * h;
            a2 += W[2][k] * h;
            a3 += W[3][k] * h;
            a4 += W[4][k] * h;
            a5 += W[5][k] * h;
        }
#pragma unroll
        for (int st = 16; st > 0; st >>= 1) {
            a0 += __shfl_xor_sync(0xffffffffu, a0, st);
            a1 += __shfl_xor_sync(0xffffffffu, a1, st);
            a2 += __shfl_xor_sync(0xffffffffu, a2, st);
            a3 += __shfl_xor_sync(0xffffffffu, a3, st);
            a4 += __shfl_xor_sync(0xffffffffu, a4, st);
            a5 += __shfl_xor_sync(0xffffffffu, a5, st);
        }
        if (l < 6) {
            float my = (l == 0) ? a0 : (l == 1) ? a1 : (l == 2) ? a2
                      : (l == 3) ? a3 : (l == 4) ? a4 : a5;
            gate_sh[q_h] = my + xval + bias_h;
        }
        __syncthreads();

        int par = t & 1;
        unsigned tag = (unsigned)(t + 1);
        if (tid < 12) {
            float iv = sigf(gate_sh[tid]);
            float fv = sigf(gate_sh[12 + tid]);
            float gv = tanh_fast(gate_sh[24 + tid]);
            float ov = sigf(gate_sh[36 + tid]);
            cstate = fv * cstate + iv * gv;
            float hv = ov * tanh_fast(cstate);
            int hidx = cid * 12 + tid;
            unsigned long long pk = ((unsigned long long)tag << 32) |
                                    (unsigned)__float_as_int(hv);
            stvol64(&g_hpack[dir][par][hidx], pk);
            g_tok[trow][dir * HID + hidx] = hv;
        }

        // gather: issue BOTH poll loads before spinning (overlap the two L2 trips)
        const unsigned long long* hp = &g_hpack[dir][par][0];
        unsigned long long v1 = ldvol64(hp + tid);
        unsigned long long v2 = 0ULL;
        if (tid < 128) v2 = ldvol64(hp + tid + 256);
        while ((unsigned)(v1 >> 32) != tag) v1 = ldvol64(hp + tid);
        h_sh[tid] = __int_as_float((int)(unsigned)v1);
        if (tid < 128) {
            while ((unsigned)(v2 >> 32) != tag) v2 = ldvol64(hp + tid + 256);
            h_sh[tid + 256] = __int_as_float((int)(unsigned)v2);
        }
        __syncthreads();

        xval = xnext;
    }
}

// ---------------- 3-phase parallel scan over tok ----------------
__global__ void scan1_kernel() {
    int b = blockIdx.x;
    for (int d = threadIdx.x; d < 2 * HID; d += 256) {
        float s = 0.f;
        for (int r = 0; r < 128; r++) s += g_tok[b * 128 + r][d];
        g_csum[b][d] = s;
    }
}
__global__ void scan2_kernel() {
    int d = threadIdx.x;
    float run = 0.f;
    for (int b = 0; b < 32; b++) {
        float v = g_csum[b][d];
        g_csum[b][d] = run;
        run += v;
    }
}
__global__ void scan3_kernel() {
    int b = blockIdx.x;
    for (int d = threadIdx.x; d < 2 * HID; d += 256) {
        float run = g_csum[b][d];
        if (b == 0) g_prefix[0][d] = 0.f;
        for (int r = 0; r < 128; r++) {
            run += g_tok[b * 128 + r][d];
            g_prefix[b * 128 + r + 1][d] = run;
        }
    }
}

// ---------------- event embeddings ----------------
__global__ void event_kernel(const void* __restrict__ lab_ev) {
    int d = blockIdx.x * blockDim.x + threadIdx.x;
    int e = blockIdx.y;
    if (d >= 2 * HID) return;
    long long st = fetch_idx(lab_ev, 0, 2LL * e);
    long long en = fetch_idx(lab_ev, 0, 2LL * e + 1);
    g_evemb[e][d] = (g_prefix[en][d] - g_prefix[st][d]) / (float)(en - st);
}

// ---------------- fold W1 into [A|B|C] ----------------
__global__ void wprep_kernel(const float* __restrict__ w1) {
    int k = blockIdx.x * blockDim.x + threadIdx.x;
    int n = blockIdx.y;
    if (k >= K3) return;
    int seg = k / 768, kk = k - seg * 768;
    const float* r = w1 + (long long)n * 3072;
    float v;
    if (seg == 0) v = r[kk] + r[1536 + kk];
    else if (seg == 1) v = r[768 + kk] - r[1536 + kk];
    else v = r[2304 + kk];
    g_wp[n][k] = v;
}

// ---------------- scores + log-softmax + CE + loss ----------------
__global__ void scores_kernel(const float* __restrict__ w3, const float* __restrict__ b3,
                              const void* __restrict__ labt, float* __restrict__ out,
                              int loss_off) {
    __shared__ float w3s[4][256];
    __shared__ float ce_sh[8];
    int tid = threadIdx.x;
    int wp = tid >> 5, l = tid & 31;
    for (int i = tid; i < 1024; i += 256) w3s[i >> 8][i & 255] = w3[i];
    __syncthreads();

    int p = blockIdx.x * 8 + wp;
    const float* h2r = &g_h2[p][0];
    float hv[8];
#pragma unroll
    for (int k = 0; k < 8; k++) hv[k] = h2r[l + 32 * k];
    float s[4];
#pragma unroll
    for (int j = 0; j < 4; j++) {
        float t = 0.f;
#pragma unroll
        for (int k = 0; k < 8; k++) t += hv[k] * w3s[j][l + 32 * k];
        t += __shfl_xor_sync(0xffffffffu, t, 16);
        t += __shfl_xor_sync(0xffffffffu, t, 8);
        t += __shfl_xor_sync(0xffffffffu, t, 4);
        t += __shfl_xor_sync(0xffffffffu, t, 2);
        t += __shfl_xor_sync(0xffffffffu, t, 1);
        s[j] = t + b3[j];
    }
    if (l == 0) {
        float m = fmaxf(fmaxf(s[0], s[1]), fmaxf(s[2], s[3]));
        float se = expf(s[0] - m) + expf(s[1] - m) + expf(s[2] - m) + expf(s[3] - m);
        float lse = m + logf(se);
        long long y = fetch_idx(labt, 2, p);
        float sy = (y == 0) ? s[0] : (y == 1) ? s[1] : (y == 2) ? s[2] : s[3];
        float* o = out + loss_off + 4LL * p;
        o[0] = s[0]; o[1] = s[1]; o[2] = s[2]; o[3] = s[3];
        ce_sh[wp] = lse - sy;
    }
    __syncthreads();
    if (tid == 0 && loss_off) {
        float t = 0.f;
#pragma unroll
        for (int i = 0; i < 8; i++) t += ce_sh[i];
        atomicAdd(out, t);
    }
}

// ---------------- launch ----------------
extern "C" void kernel_launch(void* const* d_in, const int* in_sizes, int n_in,
                              void* d_out, int out_size) {
    const float* tokemb = (const float*)d_in[0];
    const float* w_ih_f = (const float*)d_in[1];
    const float* w_hh_f = (const float*)d_in[2];
    const float* b_f = (const float*)d_in[3];
    const float* w_ih_b = (const float*)d_in[4];
    const float* w_hh_b = (const float*)d_in[5];
    const float* b_b = (const float*)d_in[6];
    const float* w1 = (const float*)d_in[7];
    const float* b1 = (const float*)d_in[8];
    const float* w2 = (const float*)d_in[9];
    const float* b2 = (const float*)d_in[10];
    const float* w3 = (const float*)d_in[11];
    const float* b3 = (const float*)d_in[12];
    const void* lab_ev = d_in[13];
    const void* pairs = d_in[14];
    const void* labt = d_in[15];
    float* out = (float*)d_out;
    int loss_off = (out_size > 4 * PN_) ? 1 : 0;

    void *p_xg, *p_h1, *p_h2;
    cudaGetSymbolAddress(&p_xg, g_xg);
    cudaGetSymbolAddress(&p_h1, g_h1);
    cudaGetSymbolAddress(&p_h2, g_h2);
    float* xg0 = (float*)p_xg;
    float* xg1 = xg0 + (long long)LSEQ * G4;

    detect_kernel<<<1, 1>>>(lab_ev, pairs, labt);
    init_kernel<<<32, 256>>>(out, loss_off);

    // input-side gate preactivations (fp32, exact — feeds the recurrence)
    sgemm_nt<<<dim3(G4 / BN, LSEQ / BM), 256>>>(tokemb, w_ih_f, xg0, LSEQ, G4, DIM, nullptr, 0);
    sgemm_nt<<<dim3(G4 / BN, LSEQ / BM), 256>>>(tokemb, w_ih_b, xg1, LSEQ, G4, DIM, nullptr, 0);

    // recurrence: 32 CTAs per direction, both directions concurrent (R4 structure)
    lstm_kernel<<<64, 256>>>(w_hh_f, b_f, w_hh_b, b_b);

    // 3-phase prefix scan + event embeddings
    scan1_kernel<<<32, 256>>>();
    scan2_kernel<<<1, 2 * HID>>>();
    scan3_kernel<<<32, 256>>>();
    event_kernel<<<dim3(3, EN_), 256>>>(lab_ev);

    // folded pair MLP: W1 fold, then fused feat-gather GEMM (tf32), then GEMM2
    wprep_kernel<<<dim3(9, DIM), 256>>>(w1);
    tgemm_feat<<<dim3(DIM / 128, PN_ / 128), 256>>>(pairs, (float*)p_h1, b1);
    tgemm_nt<<<dim3(256 / 128, PN_ / 128), 256>>>((const float*)p_h1, w2, (float*)p_h2,
                                                  PN_, 256, DIM, b2, 1);

    // scores + loss
    scores_kernel<<<PN_ / 8, 256>>>(w3, b3, labt, out, loss_off);
}

// round 7
// speedup vs baseline: 1.5046x; 1.0777x over previous
#include <cuda_runtime.h>
#include <cstdint>

#define LSEQ 4096
#define DIM 768
#define HID 384
#define G4 1536
#define EN_ 32768
#define PN_ 32768
#define K3 2304   // 3*768 folded-K for pair MLP

// ---------------- scratch (device globals; no allocation allowed) ----------------
__device__ float g_xg[2][LSEQ][G4];
__device__ float g_tok[LSEQ][2 * HID];
__device__ float g_prefix[LSEQ + 1][2 * HID];
__device__ float g_csum[32][2 * HID];
__device__ float g_evemb[EN_][2 * HID];
__device__ float g_wp[DIM][K3];
__device__ float g_h1[PN_][DIM];
__device__ float g_h2[PN_][256];
__device__ unsigned long long g_hpack[2][2][HID];  // fallback path: (tag<<32)|f32
__device__ int g_is64[3];

// ---------------- helpers ----------------
__device__ __forceinline__ long long fetch_idx(const void* p, int which, long long i) {
    if (g_is64[which]) return ((const long long*)p)[i];
    return (long long)((const int*)p)[i];
}
__device__ __forceinline__ float sigf(float x) { return 1.f / (1.f + __expf(-x)); }
__device__ __forceinline__ float tanh_fast(float x) {
    x = fminf(15.f, fmaxf(-15.f, x));
    float e = __expf(-2.f * x);
    return (1.f - e) / (1.f + e);
}
__device__ __forceinline__ unsigned long long ldvol64(const unsigned long long* p) {
    unsigned long long v;
    asm volatile("ld.volatile.global.b64 %0, [%1];" : "=l"(v) : "l"(p));
    return v;
}
__device__ __forceinline__ void stvol64(unsigned long long* p, unsigned long long v) {
    asm volatile("st.volatile.global.b64 [%0], %1;" :: "l"(p), "l"(v));
}
__device__ __forceinline__ unsigned f2tf32(float f) {
    unsigned r;
    asm("cvt.rna.tf32.f32 %0, %1;" : "=r"(r) : "f"(f));
    return r;
}
__device__ __forceinline__ unsigned smem_u32(const void* p) {
    return (unsigned)__cvta_generic_to_shared(p);
}
__device__ __forceinline__ void st_cluster_f32(unsigned laddr, int rank, float v) {
    unsigned r;
    asm volatile("mapa.shared::cluster.u32 %0, %1, %2;" : "=r"(r) : "r"(laddr), "r"(rank));
    asm volatile("st.shared::cluster.f32 [%0], %1;" :: "r"(r), "f"(v));
}

// ---------------- dtype detection + init ----------------
__global__ void detect_kernel(const void* lab_ev, const void* pairs, const void* labt) {
    if (threadIdx.x == 0) {
        const int* a = (const int*)lab_ev;
        int nz = 0;
        for (int i = 0; i < 64; i++) nz |= a[2 * i + 1];
        g_is64[0] = (nz == 0);
        const int* b = (const int*)pairs;
        nz = 0;
        for (int i = 0; i < 64; i++) nz |= b[2 * i + 1];
        g_is64[1] = (nz == 0);
        const int* c = (const int*)labt;
        nz = 0;
        for (int i = 0; i < 64; i++) nz |= c[2 * i + 1];
        g_is64[2] = (nz == 0);
    }
}

__global__ void init_kernel(float* out, int loss_off) {
    int i = blockIdx.x * blockDim.x + threadIdx.x;
    if (i < 2 * 2 * HID) ((unsigned long long*)g_hpack)[i] = 0ULL;
    if (i == 0 && loss_off) out[0] = 0.f;
}

// ---------------- fp32 SIMT GEMM (xgate; exact) ----------------
#define BM 128
#define BN 128
#define BKG 16
__global__ void __launch_bounds__(256) sgemm_nt(const float* __restrict__ A,
                                                const float* __restrict__ B,
                                                float* __restrict__ C,
                                                int M, int N, int K,
                                                const float* __restrict__ bias, int relu) {
    __shared__ float As[BKG][BM];
    __shared__ float Bs[BKG][BN];
    int bm = blockIdx.y, bn = blockIdx.x;
    int tid = threadIdx.x;
    int tx = tid & 15, ty = tid >> 4;
    const float* Ab = A + (long long)bm * BM * K;
    const float* Bb = B + (long long)bn * BN * K;

    float acc[8][8];
#pragma unroll
    for (int i = 0; i < 8; i++)
#pragma unroll
        for (int j = 0; j < 8; j++) acc[i][j] = 0.f;

    float4 pa[2], pb[2];
#pragma unroll
    for (int b = 0; b < 2; b++) {
        int f = tid + b * 256;
        int row = f >> 2, c4 = f & 3;
        pa[b] = *(const float4*)(Ab + (long long)row * K + c4 * 4);
        pb[b] = *(const float4*)(Bb + (long long)row * K + c4 * 4);
    }

    for (int k0 = 0; k0 < K; k0 += BKG) {
#pragma unroll
        for (int b = 0; b < 2; b++) {
            int f = tid + b * 256;
            int row = f >> 2, c4 = f & 3;
            As[c4 * 4 + 0][row] = pa[b].x;
            As[c4 * 4 + 1][row] = pa[b].y;
            As[c4 * 4 + 2][row] = pa[b].z;
            As[c4 * 4 + 3][row] = pa[b].w;
            Bs[c4 * 4 + 0][row] = pb[b].x;
            Bs[c4 * 4 + 1][row] = pb[b].y;
            Bs[c4 * 4 + 2][row] = pb[b].z;
            Bs[c4 * 4 + 3][row] = pb[b].w;
        }
        __syncthreads();
        if (k0 + BKG < K) {
#pragma unroll
            for (int b = 0; b < 2; b++) {
                int f = tid + b * 256;
                int row = f >> 2, c4 = f & 3;
                pa[b] = *(const float4*)(Ab + (long long)row * K + (k0 + BKG) + c4 * 4);
                pb[b] = *(const float4*)(Bb + (long long)row * K + (k0 + BKG) + c4 * 4);
            }
        }
#pragma unroll
        for (int kk = 0; kk < BKG; kk++) {
            float a[8], bq[8];
            *(float4*)&a[0] = *(const float4*)&As[kk][ty * 8];
            *(float4*)&a[4] = *(const float4*)&As[kk][ty * 8 + 4];
            *(float4*)&bq[0] = *(const float4*)&Bs[kk][tx * 8];
            *(float4*)&bq[4] = *(const float4*)&Bs[kk][tx * 8 + 4];
#pragma unroll
            for (int i = 0; i < 8; i++)
#pragma unroll
                for (int j = 0; j < 8; j++) acc[i][j] += a[i] * bq[j];
        }
        __syncthreads();
    }

#pragma unroll
    for (int i = 0; i < 8; i++) {
        long long m = (long long)bm * BM + ty * 8 + i;
#pragma unroll
        for (int j = 0; j < 8; j += 4) {
            int n = bn * BN + tx * 8 + j;
            float4 v;
            v.x = acc[i][j + 0];
            v.y = acc[i][j + 1];
            v.z = acc[i][j + 2];
            v.w = acc[i][j + 3];
            if (bias) {
                v.x += bias[n + 0];
                v.y += bias[n + 1];
                v.z += bias[n + 2];
                v.w += bias[n + 3];
            }
            if (relu) {
                v.x = fmaxf(v.x, 0.f);
                v.y = fmaxf(v.y, 0.f);
                v.z = fmaxf(v.z, 0.f);
                v.w = fmaxf(v.w, 0.f);
            }
            *(float4*)(C + m * N + n) = v;
        }
    }
}

// ---------------- tf32 tensor-core GEMM (round-2 known-good layout) ----------------
#define TPAD 36
__global__ void __launch_bounds__(256) tgemm_nt(const float* __restrict__ A,
                                                const float* __restrict__ B,
                                                float* __restrict__ C,
                                                int M, int N, int K,
                                                const float* __restrict__ bias, int relu) {
    __shared__ unsigned As[128 * TPAD];
    __shared__ unsigned Bs[128 * TPAD];
    int bm = blockIdx.y, bn = blockIdx.x;
    int tid = threadIdx.x;
    int wid = tid >> 5, l = tid & 31;
    int wm = wid & 3, wn = wid >> 2;
    int gr = l >> 2, gc = l & 3;
    const float* Ab = A + (long long)bm * 128 * K;
    const float* Bb = B + (long long)bn * 128 * K;

    float acc[2][8][4];
#pragma unroll
    for (int mi = 0; mi < 2; mi++)
#pragma unroll
        for (int ni = 0; ni < 8; ni++)
#pragma unroll
            for (int c = 0; c < 4; c++) acc[mi][ni][c] = 0.f;

    int row[4], qk[4];
    float4 ra[4], rb[4];
#pragma unroll
    for (int i = 0; i < 4; i++) {
        int idx = tid + i * 256;
        row[i] = idx >> 3;
        qk[i] = idx & 7;
        ra[i] = *(const float4*)(Ab + (long long)row[i] * K + qk[i] * 4);
        rb[i] = *(const float4*)(Bb + (long long)row[i] * K + qk[i] * 4);
    }

    for (int k0 = 0; k0 < K; k0 += 32) {
#pragma unroll
        for (int i = 0; i < 4; i++) {
            int base = row[i] * TPAD + qk[i] * 4;
            As[base + 0] = f2tf32(ra[i].x);
            As[base + 1] = f2tf32(ra[i].y);
            As[base + 2] = f2tf32(ra[i].z);
            As[base + 3] = f2tf32(ra[i].w);
            Bs[base + 0] = f2tf32(rb[i].x);
            Bs[base + 1] = f2tf32(rb[i].y);
            Bs[base + 2] = f2tf32(rb[i].z);
            Bs[base + 3] = f2tf32(rb[i].w);
        }
        __syncthreads();
        if (k0 + 32 < K) {
#pragma unroll
            for (int i = 0; i < 4; i++) {
                ra[i] = *(const float4*)(Ab + (long long)row[i] * K + (k0 + 32) + qk[i] * 4);
                rb[i] = *(const float4*)(Bb + (long long)row[i] * K + (k0 + 32) + qk[i] * 4);
            }
        }
#pragma unroll
        for (int ks = 0; ks < 4; ks++) {
            unsigned a[2][4];
#pragma unroll
            for (int mi = 0; mi < 2; mi++) {
                int baseA = (wm * 32 + mi * 16 + gr) * TPAD + ks * 8 + gc;
                a[mi][0] = As[baseA];
                a[mi][1] = As[baseA + 8 * TPAD];
                a[mi][2] = As[baseA + 4];
                a[mi][3] = As[baseA + 8 * TPAD + 4];
            }
#pragma unroll
            for (int ni = 0; ni < 8; ni++) {
                int baseB = (wn * 64 + ni * 8 + gr) * TPAD + ks * 8 + gc;
                unsigned b0 = Bs[baseB];
                unsigned b1 = Bs[baseB + 4];
#pragma unroll
                for (int mi = 0; mi < 2; mi++) {
                    asm volatile(
                        "mma.sync.aligned.m16n8k8.row.col.f32.tf32.tf32.f32 "
                        "{%0,%1,%2,%3}, {%4,%5,%6,%7}, {%8,%9}, {%0,%1,%2,%3};\n"
                        : "+f"(acc[mi][ni][0]), "+f"(acc[mi][ni][1]),
                          "+f"(acc[mi][ni][2]), "+f"(acc[mi][ni][3])
                        : "r"(a[mi][0]), "r"(a[mi][1]), "r"(a[mi][2]), "r"(a[mi][3]),
                          "r"(b0), "r"(b1));
                }
            }
        }
        __syncthreads();
    }

#pragma unroll
    for (int mi = 0; mi < 2; mi++) {
#pragma unroll
        for (int ni = 0; ni < 8; ni++) {
            int rowc = bm * 128 + wm * 32 + mi * 16 + gr;
            int colc = bn * 128 + wn * 64 + ni * 8 + 2 * gc;
            float b0v = bias ? bias[colc] : 0.f;
            float b1v = bias ? bias[colc + 1] : 0.f;
            float2 v0, v1;
            v0.x = acc[mi][ni][0] + b0v;
            v0.y = acc[mi][ni][1] + b1v;
            v1.x = acc[mi][ni][2] + b0v;
            v1.y = acc[mi][ni][3] + b1v;
            if (relu) {
                v0.x = fmaxf(v0.x, 0.f);
                v0.y = fmaxf(v0.y, 0.f);
                v1.x = fmaxf(v1.x, 0.f);
                v1.y = fmaxf(v1.y, 0.f);
            }
            *(float2*)(C + (long long)rowc * N + colc) = v0;
            *(float2*)(C + (long long)(rowc + 8) * N + colc) = v1;
        }
    }
}

// ---------------- fused feat+GEMM1 (unchanged from R6) ----------------
__device__ __forceinline__ float4 feat_lda(const int2* pr_sh, int lrow, int k) {
    int seg = k / 768, kk = k - seg * 768;
    int2 pr = pr_sh[lrow];
    if (seg == 0) return *(const float4*)&g_evemb[pr.x][kk];
    if (seg == 1) return *(const float4*)&g_evemb[pr.y][kk];
    float4 a = *(const float4*)&g_evemb[pr.x][kk];
    float4 b = *(const float4*)&g_evemb[pr.y][kk];
    return make_float4(a.x * b.x, a.y * b.y, a.z * b.z, a.w * b.w);
}

__global__ void __launch_bounds__(256) tgemm_feat(const void* __restrict__ pairs,
                                                  float* __restrict__ C,
                                                  const float* __restrict__ bias) {
    const int N = DIM, K = K3;
    __shared__ unsigned As[128 * TPAD];
    __shared__ unsigned Bs[128 * TPAD];
    __shared__ int2 pr_sh[128];
    int bm = blockIdx.y, bn = blockIdx.x;
    int tid = threadIdx.x;
    int wid = tid >> 5, l = tid & 31;
    int wm = wid & 3, wn = wid >> 2;
    int gr = l >> 2, gc = l & 3;
    const float* Bb = &g_wp[bn * 128][0];

    if (tid < 128) {
        long long p = (long long)bm * 128 + tid;
        pr_sh[tid] = make_int2((int)fetch_idx(pairs, 1, 2 * p),
                               (int)fetch_idx(pairs, 1, 2 * p + 1));
    }
    __syncthreads();

    float acc[2][8][4];
#pragma unroll
    for (int mi = 0; mi < 2; mi++)
#pragma unroll
        for (int ni = 0; ni < 8; ni++)
#pragma unroll
            for (int c = 0; c < 4; c++) acc[mi][ni][c] = 0.f;

    int row[4], qk[4];
    float4 ra[4], rb[4];
#pragma unroll
    for (int i = 0; i < 4; i++) {
        int idx = tid + i * 256;
        row[i] = idx >> 3;
        qk[i] = idx & 7;
        ra[i] = feat_lda(pr_sh, row[i], qk[i] * 4);
        rb[i] = *(const float4*)(Bb + (long long)row[i] * K + qk[i] * 4);
    }

    for (int k0 = 0; k0 < K; k0 += 32) {
#pragma unroll
        for (int i = 0; i < 4; i++) {
            int base = row[i] * TPAD + qk[i] * 4;
            As[base + 0] = f2tf32(ra[i].x);
            As[base + 1] = f2tf32(ra[i].y);
            As[base + 2] = f2tf32(ra[i].z);
            As[base + 3] = f2tf32(ra[i].w);
            Bs[base + 0] = f2tf32(rb[i].x);
            Bs[base + 1] = f2tf32(rb[i].y);
            Bs[base + 2] = f2tf32(rb[i].z);
            Bs[base + 3] = f2tf32(rb[i].w);
        }
        __syncthreads();
        if (k0 + 32 < K) {
#pragma unroll
            for (int i = 0; i < 4; i++) {
                ra[i] = feat_lda(pr_sh, row[i], (k0 + 32) + qk[i] * 4);
                rb[i] = *(const float4*)(Bb + (long long)row[i] * K + (k0 + 32) + qk[i] * 4);
            }
        }
#pragma unroll
        for (int ks = 0; ks < 4; ks++) {
            unsigned a[2][4];
#pragma unroll
            for (int mi = 0; mi < 2; mi++) {
                int baseA = (wm * 32 + mi * 16 + gr) * TPAD + ks * 8 + gc;
                a[mi][0] = As[baseA];
                a[mi][1] = As[baseA + 8 * TPAD];
                a[mi][2] = As[baseA + 4];
                a[mi][3] = As[baseA + 8 * TPAD + 4];
            }
#pragma unroll
            for (int ni = 0; ni < 8; ni++) {
                int baseB = (wn * 64 + ni * 8 + gr) * TPAD + ks * 8 + gc;
                unsigned b0 = Bs[baseB];
                unsigned b1 = Bs[baseB + 4];
#pragma unroll
                for (int mi = 0; mi < 2; mi++) {
                    asm volatile(
                        "mma.sync.aligned.m16n8k8.row.col.f32.tf32.tf32.f32 "
                        "{%0,%1,%2,%3}, {%4,%5,%6,%7}, {%8,%9}, {%0,%1,%2,%3};\n"
                        : "+f"(acc[mi][ni][0]), "+f"(acc[mi][ni][1]),
                          "+f"(acc[mi][ni][2]), "+f"(acc[mi][ni][3])
                        : "r"(a[mi][0]), "r"(a[mi][1]), "r"(a[mi][2]), "r"(a[mi][3]),
                          "r"(b0), "r"(b1));
                }
            }
        }
        __syncthreads();
    }

#pragma unroll
    for (int mi = 0; mi < 2; mi++) {
#pragma unroll
        for (int ni = 0; ni < 8; ni++) {
            int rowc = bm * 128 + wm * 32 + mi * 16 + gr;
            int colc = bn * 128 + wn * 64 + ni * 8 + 2 * gc;
            float b0v = bias[colc];
            float b1v = bias[colc + 1];
            float2 v0, v1;
            v0.x = fmaxf(acc[mi][ni][0] + b0v, 0.f);
            v0.y = fmaxf(acc[mi][ni][1] + b1v, 0.f);
            v1.x = fmaxf(acc[mi][ni][2] + b0v, 0.f);
            v1.y = fmaxf(acc[mi][ni][3] + b1v, 0.f);
            *(float2*)(C + (long long)rowc * N + colc) = v0;
            *(float2*)(C + (long long)(rowc + 8) * N + colc) = v1;
        }
    }
}

// ---------------- LSTM: cluster-16 DSMEM exchange (primary path) ----------------
// Grid 32, cluster {16,1,1}: dir = bid>>4, cid = bid&15. CTA owns h rows
// [cid*24, cid*24+24) => 96 gate rows. Warp w owns 12 gate rows q=w*12+i,
// lane l owns h-cols {l+32k, k<12} (W = 144 regs).
// Exchange: 24 act-threads push h to all 16 CTAs' h_buf[parity] via DSMEM,
// then ONE barrier.cluster per step. No L2 involvement.
__global__ void __launch_bounds__(256, 1) lstm_cluster_kernel(const float* __restrict__ w_hh_f,
                                                              const float* __restrict__ b_f,
                                                              const float* __restrict__ w_hh_b,
                                                              const float* __restrict__ b_b) {
    int bid = blockIdx.x;
    int dir = bid >> 4;
    int cid = bid & 15;
    const float* whh = dir ? w_hh_b : w_hh_f;
    const float* bb = dir ? b_b : b_f;
    int tid = threadIdx.x;
    int w = tid >> 5, l = tid & 31;

    __shared__ float h_buf[2][HID];
    __shared__ float gate_sh[96];

    float W[12][12];
#pragma unroll
    for (int i = 0; i < 12; i++) {
        int q = w * 12 + i;
        int grow = (q / 24) * HID + cid * 24 + (q % 24);
#pragma unroll
        for (int k = 0; k < 12; k++) W[i][k] = whh[(long long)grow * HID + (l + 32 * k)];
    }
    int q_h = w * 12 + l;  // valid only for l < 12
    int colg = (l < 12) ? ((q_h / 24) * HID + cid * 24 + (q_h % 24)) : 0;
    float bias_h = (l < 12) ? bb[colg] : 0.f;
    const float* xg = &g_xg[dir][0][0];

    for (int i = tid; i < 2 * HID; i += 256) ((float*)h_buf)[i] = 0.f;
    __syncthreads();
    // protect zeroed buffers from early peers' pushes
    asm volatile("barrier.cluster.arrive.aligned;" ::: "memory");
    asm volatile("barrier.cluster.wait.aligned;" ::: "memory");

    float cstate = 0.f;
    int trow0 = dir ? (LSEQ - 1) : 0;
    float xval = (l < 12) ? __ldg(xg + (long long)trow0 * G4 + colg) : 0.f;

    for (int t = 0; t < LSEQ; t++) {
        int trow = dir ? (LSEQ - 1 - t) : t;
        float xnext = 0.f;
        if (l < 12 && t + 1 < LSEQ) {
            int trn = dir ? (LSEQ - 2 - t) : (t + 1);
            xnext = __ldg(xg + (long long)trn * G4 + colg);
        }
        int par = t & 1;
        int parn = par ^ 1;

        // matvec from local double buffer (filled by peers last step)
        float hk[12];
#pragma unroll
        for (int k = 0; k < 12; k++) hk[k] = h_buf[par][l + 32 * k];
        float a[12];
#pragma unroll
        for (int i = 0; i < 12; i++) a[i] = 0.f;
#pragma unroll
        for (int k = 0; k < 12; k++) {
            float h = hk[k];
#pragma unroll
            for (int i = 0; i < 12; i++) a[i] += W[i][k] * h;
        }
#pragma unroll
        for (int st = 16; st > 0; st >>= 1) {
#pragma unroll
            for (int i = 0; i < 12; i++) a[i] += __shfl_xor_sync(0xffffffffu, a[i], st);
        }
        if (l < 12) {
            float my = 0.f;
#pragma unroll
            for (int i = 0; i < 12; i++)
                if (l == i) my = a[i];
            gate_sh[q_h] = my + xval + bias_h;
        }
        __syncthreads();

        if (tid < 24) {
            float iv = sigf(gate_sh[tid]);
            float fv = sigf(gate_sh[24 + tid]);
            float gv = tanh_fast(gate_sh[48 + tid]);
            float ov = sigf(gate_sh[72 + tid]);
            cstate = fv * cstate + iv * gv;
            float hv = ov * tanh_fast(cstate);
            int hidx = cid * 24 + tid;
            g_tok[trow][dir * HID + hidx] = hv;
            unsigned laddr = smem_u32(&h_buf[parn][hidx]);
#pragma unroll
            for (int p = 0; p < 16; p++) st_cluster_f32(laddr, p, hv);
        }

        // one cluster rendezvous per step (release/acquire orders DSMEM stores)
        asm volatile("barrier.cluster.arrive.aligned;" ::: "memory");
        asm volatile("barrier.cluster.wait.aligned;" ::: "memory");

        xval = xnext;
    }
}

// ---------------- LSTM fallback: R6 global packed exchange ----------------
__global__ void __launch_bounds__(256, 1) lstm_kernel(const float* __restrict__ w_hh_f,
                                                      const float* __restrict__ b_f,
                                                      const float* __restrict__ w_hh_b,
                                                      const float* __restrict__ b_b) {
    int dir = blockIdx.x >> 5;
    int cid = blockIdx.x & 31;
    const float* whh = dir ? w_hh_b : w_hh_f;
    const float* bb = dir ? b_b : b_f;
    int tid = threadIdx.x;
    int w = tid >> 5, l = tid & 31;

    __shared__ float h_sh[HID];
    __shared__ float gate_sh[48];

    float W[6][12];
#pragma unroll
    for (int i = 0; i < 6; i++) {
        int q = w * 6 + i;
        int grow = (q / 12) * HID + cid * 12 + (q % 12);
#pragma unroll
        for (int k = 0; k < 12; k++) W[i][k] = whh[(long long)grow * HID + (l + 32 * k)];
    }
    int q_h = w * 6 + l;
    int gx = (l < 6) ? ((q_h / 12) * HID + cid * 12 + (q_h % 12)) : 0;
    float bias_h = (l < 6) ? bb[gx] : 0.f;
    const float* xg = &g_xg[dir][0][0];

    float cstate = 0.f;
    for (int i = tid; i < HID; i += 256) h_sh[i] = 0.f;
    __syncthreads();

    int trow0 = dir ? (LSEQ - 1) : 0;
    float xval = (l < 6) ? __ldg(xg + (long long)trow0 * G4 + gx) : 0.f;

    for (int t = 0; t < LSEQ; t++) {
        int trow = dir ? (LSEQ - 1 - t) : t;
        float xnext = 0.f;
        if (l < 6 && t + 1 < LSEQ) {
            int trn = dir ? (LSEQ - 2 - t) : (t + 1);
            xnext = __ldg(xg + (long long)trn * G4 + gx);
        }

        float hk[12];
#pragma unroll
        for (int k = 0; k < 12; k++) hk[k] = h_sh[l + 32 * k];
        float a0 = 0.f, a1 = 0.f, a2 = 0.f, a3 = 0.f, a4 = 0.f, a5 = 0.f;
#pragma unroll
        for (int k = 0; k < 12; k++) {
            float h = hk[k];
            a0 += W[0][k] * h;
            a1 += W[1][k] * h;
            a2 += W[2][k] * h;
            a3 += W[3][k] * h;
            a4 += W[4][k] * h;
            a5 += W[5][k] * h;
        }
#pragma unroll
        for (int st = 16; st > 0; st >>= 1) {
            a0 += __shfl_xor_sync(0xffffffffu, a0, st);
            a1 += __shfl_xor_sync(0xffffffffu, a1, st);
            a2 += __shfl_xor_sync(0xffffffffu, a2, st);
            a3 += __shfl_xor_sync(0xffffffffu, a3, st);
            a4 += __shfl_xor_sync(0xffffffffu, a4, st);
            a5 += __shfl_xor_sync(0xffffffffu, a5, st);
        }
        if (l < 6) {
            float my = (l == 0) ? a0 : (l == 1) ? a1 : (l == 2) ? a2
                      : (l == 3) ? a3 : (l == 4) ? a4 : a5;
            gate_sh[q_h] = my + xval + bias_h;
        }
        __syncthreads();

        int par = t & 1;
        unsigned tag = (unsigned)(t + 1);
        if (tid < 12) {
            float iv = sigf(gate_sh[tid]);
            float fv = sigf(gate_sh[12 + tid]);
            float gv = tanh_fast(gate_sh[24 + tid]);
            float ov = sigf(gate_sh[36 + tid]);
            cstate = fv * cstate + iv * gv;
            float hv = ov * tanh_fast(cstate);
            int hidx = cid * 12 + tid;
            unsigned long long pk = ((unsigned long long)tag << 32) |
                                    (unsigned)__float_as_int(hv);
            stvol64(&g_hpack[dir][par][hidx], pk);
            g_tok[trow][dir * HID + hidx] = hv;
        }

        const unsigned long long* hp = &g_hpack[dir][par][0];
        unsigned long long v1 = ldvol64(hp + tid);
        unsigned long long v2 = 0ULL;
        if (tid < 128) v2 = ldvol64(hp + tid + 256);
        while ((unsigned)(v1 >> 32) != tag) v1 = ldvol64(hp + tid);
        h_sh[tid] = __int_as_float((int)(unsigned)v1);
        if (tid < 128) {
            while ((unsigned)(v2 >> 32) != tag) v2 = ldvol64(hp + tid + 256);
            h_sh[tid + 256] = __int_as_float((int)(unsigned)v2);
        }
        __syncthreads();

        xval = xnext;
    }
}

// ---------------- 3-phase parallel scan over tok ----------------
__global__ void scan1_kernel() {
    int b = blockIdx.x;
    for (int d = threadIdx.x; d < 2 * HID; d += 256) {
        float s = 0.f;
        for (int r = 0; r < 128; r++) s += g_tok[b * 128 + r][d];
        g_csum[b][d] = s;
    }
}
__global__ void scan2_kernel() {
    int d = threadIdx.x;
    float run = 0.f;
    for (int b = 0; b < 32; b++) {
        float v = g_csum[b][d];
        g_csum[b][d] = run;
        run += v;
    }
}
__global__ void scan3_kernel() {
    int b = blockIdx.x;
    for (int d = threadIdx.x; d < 2 * HID; d += 256) {
        float run = g_csum[b][d];
        if (b == 0) g_prefix[0][d] = 0.f;
        for (int r = 0; r < 128; r++) {
            run += g_tok[b * 128 + r][d];
            g_prefix[b * 128 + r + 1][d] = run;
        }
    }
}

// ---------------- event embeddings ----------------
__global__ void event_kernel(const void* __restrict__ lab_ev) {
    int d = blockIdx.x * blockDim.x + threadIdx.x;
    int e = blockIdx.y;
    if (d >= 2 * HID) return;
    long long st = fetch_idx(lab_ev, 0, 2LL * e);
    long long en = fetch_idx(lab_ev, 0, 2LL * e + 1);
    g_evemb[e][d] = (g_prefix[en][d] - g_prefix[st][d]) / (float)(en - st);
}

// ---------------- fold W1 into [A|B|C] ----------------
__global__ void wprep_kernel(const float* __restrict__ w1) {
    int k = blockIdx.x * blockDim.x + threadIdx.x;
    int n = blockIdx.y;
    if (k >= K3) return;
    int seg = k / 768, kk = k - seg * 768;
    const float* r = w1 + (long long)n * 3072;
    float v;
    if (seg == 0) v = r[kk] + r[1536 + kk];
    else if (seg == 1) v = r[768 + kk] - r[1536 + kk];
    else v = r[2304 + kk];
    g_wp[n][k] = v;
}

// ---------------- scores + log-softmax + CE + loss ----------------
__global__ void scores_kernel(const float* __restrict__ w3, const float* __restrict__ b3,
                              const void* __restrict__ labt, float* __restrict__ out,
                              int loss_off) {
    __shared__ float w3s[4][256];
    __shared__ float ce_sh[8];
    int tid = threadIdx.x;
    int wp = tid >> 5, l = tid & 31;
    for (int i = tid; i < 1024; i += 256) w3s[i >> 8][i & 255] = w3[i];
    __syncthreads();

    int p = blockIdx.x * 8 + wp;
    const float* h2r = &g_h2[p][0];
    float hv[8];
#pragma unroll
    for (int k = 0; k < 8; k++) hv[k] = h2r[l + 32 * k];
    float s[4];
#pragma unroll
    for (int j = 0; j < 4; j++) {
        float t = 0.f;
#pragma unroll
        for (int k = 0; k < 8; k++) t += hv[k] * w3s[j][l + 32 * k];
        t += __shfl_xor_sync(0xffffffffu, t, 16);
        t += __shfl_xor_sync(0xffffffffu, t, 8);
        t += __shfl_xor_sync(0xffffffffu, t, 4);
        t += __shfl_xor_sync(0xffffffffu, t, 2);
        t += __shfl_xor_sync(0xffffffffu, t, 1);
        s[j] = t + b3[j];
    }
    if (l == 0) {
        float m = fmaxf(fmaxf(s[0], s[1]), fmaxf(s[2], s[3]));
        float se = expf(s[0] - m) + expf(s[1] - m) + expf(s[2] - m) + expf(s[3] - m);
        float lse = m + logf(se);
        long long y = fetch_idx(labt, 2, p);
        float sy = (y == 0) ? s[0] : (y == 1) ? s[1] : (y == 2) ? s[2] : s[3];
        float* o = out + loss_off + 4LL * p;
        o[0] = s[0]; o[1] = s[1]; o[2] = s[2]; o[3] = s[3];
        ce_sh[wp] = lse - sy;
    }
    __syncthreads();
    if (tid == 0 && loss_off) {
        float t = 0.f;
#pragma unroll
        for (int i = 0; i < 8; i++) t += ce_sh[i];
        atomicAdd(out, t);
    }
}

// ---------------- launch ----------------
extern "C" void kernel_launch(void* const* d_in, const int* in_sizes, int n_in,
                              void* d_out, int out_size) {
    const float* tokemb = (const float*)d_in[0];
    const float* w_ih_f = (const float*)d_in[1];
    const float* w_hh_f = (const float*)d_in[2];
    const float* b_f = (const float*)d_in[3];
    const float* w_ih_b = (const float*)d_in[4];
    const float* w_hh_b = (const float*)d_in[5];
    const float* b_b = (const float*)d_in[6];
    const float* w1 = (const float*)d_in[7];
    const float* b1 = (const float*)d_in[8];
    const float* w2 = (const float*)d_in[9];
    const float* b2 = (const float*)d_in[10];
    const float* w3 = (const float*)d_in[11];
    const float* b3 = (const float*)d_in[12];
    const void* lab_ev = d_in[13];
    const void* pairs = d_in[14];
    const void* labt = d_in[15];
    float* out = (float*)d_out;
    int loss_off = (out_size > 4 * PN_) ? 1 : 0;

    void *p_xg, *p_h1, *p_h2;
    cudaGetSymbolAddress(&p_xg, g_xg);
    cudaGetSymbolAddress(&p_h1, g_h1);
    cudaGetSymbolAddress(&p_h2, g_h2);
    float* xg0 = (float*)p_xg;
    float* xg1 = xg0 + (long long)LSEQ * G4;

    detect_kernel<<<1, 1>>>(lab_ev, pairs, labt);
    init_kernel<<<32, 256>>>(out, loss_off);

    sgemm_nt<<<dim3(G4 / BN, LSEQ / BM), 256>>>(tokemb, w_ih_f, xg0, LSEQ, G4, DIM, nullptr, 0);
    sgemm_nt<<<dim3(G4 / BN, LSEQ / BM), 256>>>(tokemb, w_ih_b, xg1, LSEQ, G4, DIM, nullptr, 0);

    // recurrence: cluster-16 DSMEM if supported (deterministic device query),
    // else R6 global-exchange fallback
    {
        cudaFuncSetAttribute(lstm_cluster_kernel,
                             cudaFuncAttributeNonPortableClusterSizeAllowed, 1);
        cudaLaunchConfig_t cfg = {};
        cfg.gridDim = dim3(32, 1, 1);
        cfg.blockDim = dim3(256, 1, 1);
        cfg.dynamicSmemBytes = 0;
        cudaLaunchAttribute at[1];
        at[0].id = cudaLaunchAttributeClusterDimension;
        at[0].val.clusterDim.x = 16;
        at[0].val.clusterDim.y = 1;
        at[0].val.clusterDim.z = 1;
        cfg.attrs = at;
        cfg.numAttrs = 1;
        int nclus = 0;
        cudaError_t qe = cudaOccupancyMaxActiveClusters(&nclus, lstm_cluster_kernel, &cfg);
        if (qe == cudaSuccess && nclus >= 2) {
            cudaLaunchKernelEx(&cfg, lstm_cluster_kernel, w_hh_f, b_f, w_hh_b, b_b);
        } else {
            cudaGetLastError();  // clear any sticky query error
            lstm_kernel<<<64, 256>>>(w_hh_f, b_f, w_hh_b, b_b);
        }
    }

    scan1_kernel<<<32, 256>>>();
    scan2_kernel<<<1, 2 * HID>>>();
    scan3_kernel<<<32, 256>>>();
    event_kernel<<<dim3(3, EN_), 256>>>(lab_ev);

    wprep_kernel<<<dim3(9, DIM), 256>>>(w1);
    tgemm_feat<<<dim3(DIM / 128, PN_ / 128), 256>>>(pairs, (float*)p_h1, b1);
    tgemm_nt<<<dim3(256 / 128, PN_ / 128), 256>>>((const float*)p_h1, w2, (float*)p_h2,
                                                  PN_, 256, DIM, b2, 1);

    scores_kernel<<<PN_ / 8, 256>>>(w3, b3, labt, out, loss_off);
}

// round 9
// speedup vs baseline: 1.7844x; 1.1860x over previous
#include <cuda_runtime.h>
#include <cstdint>

#define LSEQ 4096
#define DIM 768
#define HID 384
#define G4 1536
#define EN_ 32768
#define PN_ 32768
#define K3 2304   // 3*768 folded-K for pair MLP

// ---------------- scratch (device globals; no allocation allowed) ----------------
__device__ float g_xg[2][LSEQ][G4];
__device__ float g_tok[LSEQ][2 * HID];
__device__ float g_prefix[LSEQ + 1][2 * HID];
__device__ float g_csum[32][2 * HID];
__device__ float g_evemb[EN_][2 * HID];
__device__ float g_wp[DIM][K3];
__device__ float g_h1[PN_][DIM];
__device__ float g_h2[PN_][256];
__device__ unsigned long long g_hpack[2][2][HID];  // fallback path: (tag<<32)|f32
__device__ int g_is64[3];

// ---------------- helpers ----------------
__device__ __forceinline__ long long fetch_idx(const void* p, int which, long long i) {
    if (g_is64[which]) return ((const long long*)p)[i];
    return (long long)((const int*)p)[i];
}
__device__ __forceinline__ float sigf(float x) { return 1.f / (1.f + __expf(-x)); }
__device__ __forceinline__ float tanh_fast(float x) {
    x = fminf(15.f, fmaxf(-15.f, x));
    float e = __expf(-2.f * x);
    return (1.f - e) / (1.f + e);
}
__device__ __forceinline__ unsigned long long ldvol64(const unsigned long long* p) {
    unsigned long long v;
    asm volatile("ld.volatile.global.b64 %0, [%1];" : "=l"(v) : "l"(p));
    return v;
}
__device__ __forceinline__ void stvol64(unsigned long long* p, unsigned long long v) {
    asm volatile("st.volatile.global.b64 [%0], %1;" :: "l"(p), "l"(v));
}
__device__ __forceinline__ unsigned f2tf32(float f) {
    unsigned r;
    asm("cvt.rna.tf32.f32 %0, %1;" : "=r"(r) : "f"(f));
    return r;
}
__device__ __forceinline__ unsigned smem_u32(const void* p) {
    return (unsigned)__cvta_generic_to_shared(p);
}
__device__ __forceinline__ void st_cluster_f32(unsigned laddr, int rank, float v) {
    unsigned r;
    asm volatile("mapa.shared::cluster.u32 %0, %1, %2;" : "=r"(r) : "r"(laddr), "r"(rank));
    asm volatile("st.shared::cluster.f32 [%0], %1;" :: "r"(r), "f"(v));
}
// remote arrive: release-orders this thread's prior DSMEM stores for the acquirer
__device__ __forceinline__ void mbar_arrive_cluster(unsigned local_mbar, int rank) {
    asm volatile(
        "{\n\t"
        ".reg .b32 ra;\n\t"
        "mapa.shared::cluster.u32 ra, %0, %1;\n\t"
        "mbarrier.arrive.shared::cluster.b64 _, [ra];\n\t"
        "}"
        :: "r"(local_mbar), "r"(rank) : "memory");
}
__device__ __forceinline__ void mbar_init(unsigned mbar, unsigned cnt) {
    asm volatile("mbarrier.init.shared.b64 [%0], %1;" :: "r"(mbar), "r"(cnt) : "memory");
}
__device__ __forceinline__ void mbar_wait_parity_cluster(unsigned mbar, unsigned ph) {
    unsigned done;
    asm volatile(
        "{\n\t"
        ".reg .pred p;\n\t"
        "mbarrier.try_wait.parity.acquire.cluster.shared::cta.b64 p, [%1], %2;\n\t"
        "selp.b32 %0, 1, 0, p;\n\t"
        "}"
        : "=r"(done) : "r"(mbar), "r"(ph) : "memory");
    while (!done) {
        asm volatile(
            "{\n\t"
            ".reg .pred p;\n\t"
            "mbarrier.try_wait.parity.acquire.cluster.shared::cta.b64 p, [%1], %2, 0x989680;\n\t"
            "selp.b32 %0, 1, 0, p;\n\t"
            "}"
            : "=r"(done) : "r"(mbar), "r"(ph) : "memory");
    }
}

// ---------------- dtype detection + init ----------------
__global__ void detect_kernel(const void* lab_ev, const void* pairs, const void* labt) {
    if (threadIdx.x == 0) {
        const int* a = (const int*)lab_ev;
        int nz = 0;
        for (int i = 0; i < 64; i++) nz |= a[2 * i + 1];
        g_is64[0] = (nz == 0);
        const int* b = (const int*)pairs;
        nz = 0;
        for (int i = 0; i < 64; i++) nz |= b[2 * i + 1];
        g_is64[1] = (nz == 0);
        const int* c = (const int*)labt;
        nz = 0;
        for (int i = 0; i < 64; i++) nz |= c[2 * i + 1];
        g_is64[2] = (nz == 0);
    }
}

__global__ void init_kernel(float* out, int loss_off) {
    int i = blockIdx.x * blockDim.x + threadIdx.x;
    if (i < 2 * 2 * HID) ((unsigned long long*)g_hpack)[i] = 0ULL;
    if (i == 0 && loss_off) out[0] = 0.f;
}

// ---------------- fp32 SIMT GEMM (xgate; exact) ----------------
#define BM 128
#define BN 128
#define BKG 16
__global__ void __launch_bounds__(256) sgemm_nt(const float* __restrict__ A,
                                                const float* __restrict__ B,
                                                float* __restrict__ C,
                                                int M, int N, int K,
                                                const float* __restrict__ bias, int relu) {
    __shared__ float As[BKG][BM];
    __shared__ float Bs[BKG][BN];
    int bm = blockIdx.y, bn = blockIdx.x;
    int tid = threadIdx.x;
    int tx = tid & 15, ty = tid >> 4;
    const float* Ab = A + (long long)bm * BM * K;
    const float* Bb = B + (long long)bn * BN * K;

    float acc[8][8];
#pragma unroll
    for (int i = 0; i < 8; i++)
#pragma unroll
        for (int j = 0; j < 8; j++) acc[i][j] = 0.f;

    float4 pa[2], pb[2];
#pragma unroll
    for (int b = 0; b < 2; b++) {
        int f = tid + b * 256;
        int row = f >> 2, c4 = f & 3;
        pa[b] = *(const float4*)(Ab + (long long)row * K + c4 * 4);
        pb[b] = *(const float4*)(Bb + (long long)row * K + c4 * 4);
    }

    for (int k0 = 0; k0 < K; k0 += BKG) {
#pragma unroll
        for (int b = 0; b < 2; b++) {
            int f = tid + b * 256;
            int row = f >> 2, c4 = f & 3;
            As[c4 * 4 + 0][row] = pa[b].x;
            As[c4 * 4 + 1][row] = pa[b].y;
            As[c4 * 4 + 2][row] = pa[b].z;
            As[c4 * 4 + 3][row] = pa[b].w;
            Bs[c4 * 4 + 0][row] = pb[b].x;
            Bs[c4 * 4 + 1][row] = pb[b].y;
            Bs[c4 * 4 + 2][row] = pb[b].z;
            Bs[c4 * 4 + 3][row] = pb[b].w;
        }
        __syncthreads();
        if (k0 + BKG < K) {
#pragma unroll
            for (int b = 0; b < 2; b++) {
                int f = tid + b * 256;
                int row = f >> 2, c4 = f & 3;
                pa[b] = *(const float4*)(Ab + (long long)row * K + (k0 + BKG) + c4 * 4);
                pb[b] = *(const float4*)(Bb + (long long)row * K + (k0 + BKG) + c4 * 4);
            }
        }
#pragma unroll
        for (int kk = 0; kk < BKG; kk++) {
            float a[8], bq[8];
            *(float4*)&a[0] = *(const float4*)&As[kk][ty * 8];
            *(float4*)&a[4] = *(const float4*)&As[kk][ty * 8 + 4];
            *(float4*)&bq[0] = *(const float4*)&Bs[kk][tx * 8];
            *(float4*)&bq[4] = *(const float4*)&Bs[kk][tx * 8 + 4];
#pragma unroll
            for (int i = 0; i < 8; i++)
#pragma unroll
                for (int j = 0; j < 8; j++) acc[i][j] += a[i] * bq[j];
        }
        __syncthreads();
    }

#pragma unroll
    for (int i = 0; i < 8; i++) {
        long long m = (long long)bm * BM + ty * 8 + i;
#pragma unroll
        for (int j = 0; j < 8; j += 4) {
            int n = bn * BN + tx * 8 + j;
            float4 v;
            v.x = acc[i][j + 0];
            v.y = acc[i][j + 1];
            v.z = acc[i][j + 2];
            v.w = acc[i][j + 3];
            if (bias) {
                v.x += bias[n + 0];
                v.y += bias[n + 1];
                v.z += bias[n + 2];
                v.w += bias[n + 3];
            }
            if (relu) {
                v.x = fmaxf(v.x, 0.f);
                v.y = fmaxf(v.y, 0.f);
                v.z = fmaxf(v.z, 0.f);
                v.w = fmaxf(v.w, 0.f);
            }
            *(float4*)(C + m * N + n) = v;
        }
    }
}

// ---------------- tf32 tensor-core GEMM (round-2 known-good layout) ----------------
#define TPAD 36
__global__ void __launch_bounds__(256) tgemm_nt(const float* __restrict__ A,
                                                const float* __restrict__ B,
                                                float* __restrict__ C,
                                                int M, int N, int K,
                                                const float* __restrict__ bias, int relu) {
    __shared__ unsigned As[128 * TPAD];
    __shared__ unsigned Bs[128 * TPAD];
    int bm = blockIdx.y, bn = blockIdx.x;
    int tid = threadIdx.x;
    int wid = tid >> 5, l = tid & 31;
    int wm = wid & 3, wn = wid >> 2;
    int gr = l >> 2, gc = l & 3;
    const float* Ab = A + (long long)bm * 128 * K;
    const float* Bb = B + (long long)bn * 128 * K;

    float acc[2][8][4];
#pragma unroll
    for (int mi = 0; mi < 2; mi++)
#pragma unroll
        for (int ni = 0; ni < 8; ni++)
#pragma unroll
            for (int c = 0; c < 4; c++) acc[mi][ni][c] = 0.f;

    int row[4], qk[4];
    float4 ra[4], rb[4];
#pragma unroll
    for (int i = 0; i < 4; i++) {
        int idx = tid + i * 256;
        row[i] = idx >> 3;
        qk[i] = idx & 7;
        ra[i] = *(const float4*)(Ab + (long long)row[i] * K + qk[i] * 4);
        rb[i] = *(const float4*)(Bb + (long long)row[i] * K + qk[i] * 4);
    }

    for (int k0 = 0; k0 < K; k0 += 32) {
#pragma unroll
        for (int i = 0; i < 4; i++) {
            int base = row[i] * TPAD + qk[i] * 4;
            As[base + 0] = f2tf32(ra[i].x);
            As[base + 1] = f2tf32(ra[i].y);
            As[base + 2] = f2tf32(ra[i].z);
            As[base + 3] = f2tf32(ra[i].w);
            Bs[base + 0] = f2tf32(rb[i].x);
            Bs[base + 1] = f2tf32(rb[i].y);
            Bs[base + 2] = f2tf32(rb[i].z);
            Bs[base + 3] = f2tf32(rb[i].w);
        }
        __syncthreads();
        if (k0 + 32 < K) {
#pragma unroll
            for (int i = 0; i < 4; i++) {
                ra[i] = *(const float4*)(Ab + (long long)row[i] * K + (k0 + 32) + qk[i] * 4);
                rb[i] = *(const float4*)(Bb + (long long)row[i] * K + (k0 + 32) + qk[i] * 4);
            }
        }
#pragma unroll
        for (int ks = 0; ks < 4; ks++) {
            unsigned a[2][4];
#pragma unroll
            for (int mi = 0; mi < 2; mi++) {
                int baseA = (wm * 32 + mi * 16 + gr) * TPAD + ks * 8 + gc;
                a[mi][0] = As[baseA];
                a[mi][1] = As[baseA + 8 * TPAD];
                a[mi][2] = As[baseA + 4];
                a[mi][3] = As[baseA + 8 * TPAD + 4];
            }
#pragma unroll
            for (int ni = 0; ni < 8; ni++) {
                int baseB = (wn * 64 + ni * 8 + gr) * TPAD + ks * 8 + gc;
                unsigned b0 = Bs[baseB];
                unsigned b1 = Bs[baseB + 4];
#pragma unroll
                for (int mi = 0; mi < 2; mi++) {
                    asm volatile(
                        "mma.sync.aligned.m16n8k8.row.col.f32.tf32.tf32.f32 "
                        "{%0,%1,%2,%3}, {%4,%5,%6,%7}, {%8,%9}, {%0,%1,%2,%3};\n"
                        : "+f"(acc[mi][ni][0]), "+f"(acc[mi][ni][1]),
                          "+f"(acc[mi][ni][2]), "+f"(acc[mi][ni][3])
                        : "r"(a[mi][0]), "r"(a[mi][1]), "r"(a[mi][2]), "r"(a[mi][3]),
                          "r"(b0), "r"(b1));
                }
            }
        }
        __syncthreads();
    }

#pragma unroll
    for (int mi = 0; mi < 2; mi++) {
#pragma unroll
        for (int ni = 0; ni < 8; ni++) {
            int rowc = bm * 128 + wm * 32 + mi * 16 + gr;
            int colc = bn * 128 + wn * 64 + ni * 8 + 2 * gc;
            float b0v = bias ? bias[colc] : 0.f;
            float b1v = bias ? bias[colc + 1] : 0.f;
            float2 v0, v1;
            v0.x = acc[mi][ni][0] + b0v;
            v0.y = acc[mi][ni][1] + b1v;
            v1.x = acc[mi][ni][2] + b0v;
            v1.y = acc[mi][ni][3] + b1v;
            if (relu) {
                v0.x = fmaxf(v0.x, 0.f);
                v0.y = fmaxf(v0.y, 0.f);
                v1.x = fmaxf(v1.x, 0.f);
                v1.y = fmaxf(v1.y, 0.f);
            }
            *(float2*)(C + (long long)rowc * N + colc) = v0;
            *(float2*)(C + (long long)(rowc + 8) * N + colc) = v1;
        }
    }
}

// ---------------- fused feat+GEMM1 (unchanged) ----------------
__device__ __forceinline__ float4 feat_lda(const int2* pr_sh, int lrow, int k) {
    int seg = k / 768, kk = k - seg * 768;
    int2 pr = pr_sh[lrow];
    if (seg == 0) return *(const float4*)&g_evemb[pr.x][kk];
    if (seg == 1) return *(const float4*)&g_evemb[pr.y][kk];
    float4 a = *(const float4*)&g_evemb[pr.x][kk];
    float4 b = *(const float4*)&g_evemb[pr.y][kk];
    return make_float4(a.x * b.x, a.y * b.y, a.z * b.z, a.w * b.w);
}

__global__ void __launch_bounds__(256) tgemm_feat(const void* __restrict__ pairs,
                                                  float* __restrict__ C,
                                                  const float* __restrict__ bias) {
    const int N = DIM, K = K3;
    __shared__ unsigned As[128 * TPAD];
    __shared__ unsigned Bs[128 * TPAD];
    __shared__ int2 pr_sh[128];
    int bm = blockIdx.y, bn = blockIdx.x;
    int tid = threadIdx.x;
    int wid = tid >> 5, l = tid & 31;
    int wm = wid & 3, wn = wid >> 2;
    int gr = l >> 2, gc = l & 3;
    const float* Bb = &g_wp[bn * 128][0];

    if (tid < 128) {
        long long p = (long long)bm * 128 + tid;
        pr_sh[tid] = make_int2((int)fetch_idx(pairs, 1, 2 * p),
                               (int)fetch_idx(pairs, 1, 2 * p + 1));
    }
    __syncthreads();

    float acc[2][8][4];
#pragma unroll
    for (int mi = 0; mi < 2; mi++)
#pragma unroll
        for (int ni = 0; ni < 8; ni++)
#pragma unroll
            for (int c = 0; c < 4; c++) acc[mi][ni][c] = 0.f;

    int row[4], qk[4];
    float4 ra[4], rb[4];
#pragma unroll
    for (int i = 0; i < 4; i++) {
        int idx = tid + i * 256;
        row[i] = idx >> 3;
        qk[i] = idx & 7;
        ra[i] = feat_lda(pr_sh, row[i], qk[i] * 4);
        rb[i] = *(const float4*)(Bb + (long long)row[i] * K + qk[i] * 4);
    }

    for (int k0 = 0; k0 < K; k0 += 32) {
#pragma unroll
        for (int i = 0; i < 4; i++) {
            int base = row[i] * TPAD + qk[i] * 4;
            As[base + 0] = f2tf32(ra[i].x);
            As[base + 1] = f2tf32(ra[i].y);
            As[base + 2] = f2tf32(ra[i].z);
            As[base + 3] = f2tf32(ra[i].w);
            Bs[base + 0] = f2tf32(rb[i].x);
            Bs[base + 1] = f2tf32(rb[i].y);
            Bs[base + 2] = f2tf32(rb[i].z);
            Bs[base + 3] = f2tf32(rb[i].w);
        }
        __syncthreads();
        if (k0 + 32 < K) {
#pragma unroll
            for (int i = 0; i < 4; i++) {
                ra[i] = feat_lda(pr_sh, row[i], (k0 + 32) + qk[i] * 4);
                rb[i] = *(const float4*)(Bb + (long long)row[i] * K + (k0 + 32) + qk[i] * 4);
            }
        }
#pragma unroll
        for (int ks = 0; ks < 4; ks++) {
            unsigned a[2][4];
#pragma unroll
            for (int mi = 0; mi < 2; mi++) {
                int baseA = (wm * 32 + mi * 16 + gr) * TPAD + ks * 8 + gc;
                a[mi][0] = As[baseA];
                a[mi][1] = As[baseA + 8 * TPAD];
                a[mi][2] = As[baseA + 4];
                a[mi][3] = As[baseA + 8 * TPAD + 4];
            }
#pragma unroll
            for (int ni = 0; ni < 8; ni++) {
                int baseB = (wn * 64 + ni * 8 + gr) * TPAD + ks * 8 + gc;
                unsigned b0 = Bs[baseB];
                unsigned b1 = Bs[baseB + 4];
#pragma unroll
                for (int mi = 0; mi < 2; mi++) {
                    asm volatile(
                        "mma.sync.aligned.m16n8k8.row.col.f32.tf32.tf32.f32 "
                        "{%0,%1,%2,%3}, {%4,%5,%6,%7}, {%8,%9}, {%0,%1,%2,%3};\n"
                        : "+f"(acc[mi][ni][0]), "+f"(acc[mi][ni][1]),
                          "+f"(acc[mi][ni][2]), "+f"(acc[mi][ni][3])
                        : "r"(a[mi][0]), "r"(a[mi][1]), "r"(a[mi][2]), "r"(a[mi][3]),
                          "r"(b0), "r"(b1));
                }
            }
        }
        __syncthreads();
    }

#pragma unroll
    for (int mi = 0; mi < 2; mi++) {
#pragma unroll
        for (int ni = 0; ni < 8; ni++) {
            int rowc = bm * 128 + wm * 32 + mi * 16 + gr;
            int colc = bn * 128 + wn * 64 + ni * 8 + 2 * gc;
            float b0v = bias[colc];
            float b1v = bias[colc + 1];
            float2 v0, v1;
            v0.x = fmaxf(acc[mi][ni][0] + b0v, 0.f);
            v0.y = fmaxf(acc[mi][ni][1] + b1v, 0.f);
            v1.x = fmaxf(acc[mi][ni][2] + b0v, 0.f);
            v1.y = fmaxf(acc[mi][ni][3] + b1v, 0.f);
            *(float2*)(C + (long long)rowc * N + colc) = v0;
            *(float2*)(C + (long long)(rowc + 8) * N + colc) = v1;
        }
    }
}

// ---------------- LSTM: cluster-16 DSMEM + per-CTA mbarrier sync ----------------
// Grid 32, cluster {16,1,1}. CTA owns 24 h rows (96 gate rows; W=144 regs/thread).
// Step t: matvec(h_buf[t&1]) -> act -> DSMEM-push h to all peers' h_buf[(t+1)&1]
// -> 16 remote release-arrives on peers' mb[(t+1)&1] -> acquire-wait local
// mb[(t+1)&1] parity (t>>1)&1. No cluster-wide barrier in the loop.
__global__ void __launch_bounds__(256, 1) lstm_cluster_kernel(const float* __restrict__ w_hh_f,
                                                              const float* __restrict__ b_f,
                                                              const float* __restrict__ w_hh_b,
                                                              const float* __restrict__ b_b) {
    int bid = blockIdx.x;
    int dir = bid >> 4;
    int cid = bid & 15;
    const float* whh = dir ? w_hh_b : w_hh_f;
    const float* bb = dir ? b_b : b_f;
    int tid = threadIdx.x;
    int w = tid >> 5, l = tid & 31;

    __shared__ float h_buf[2][HID];
    __shared__ float gate_sh[96];
    __shared__ __align__(8) unsigned long long mb[2];

    float W[12][12];
#pragma unroll
    for (int i = 0; i < 12; i++) {
        int q = w * 12 + i;
        int grow = (q / 24) * HID + cid * 24 + (q % 24);
#pragma unroll
        for (int k = 0; k < 12; k++) W[i][k] = whh[(long long)grow * HID + (l + 32 * k)];
    }
    int q_h = w * 12 + l;  // valid only for l < 12
    int colg = (l < 12) ? ((q_h / 24) * HID + cid * 24 + (q_h % 24)) : 0;
    float bias_h = (l < 12) ? bb[colg] : 0.f;
    const float* xg = &g_xg[dir][0][0];

    unsigned mb0 = smem_u32(&mb[0]);
    unsigned mb1 = smem_u32(&mb[1]);
    if (tid == 0) {
        mbar_init(mb0, 24 * 16);
        mbar_init(mb1, 24 * 16);
    }
    for (int i = tid; i < 2 * HID; i += 256) ((float*)h_buf)[i] = 0.f;
    __syncthreads();
    // all CTAs' buffers zeroed + mbarriers initialized before any peer traffic
    asm volatile("barrier.cluster.arrive.aligned;" ::: "memory");
    asm volatile("barrier.cluster.wait.aligned;" ::: "memory");

    float cstate = 0.f;
    int trow0 = dir ? (LSEQ - 1) : 0;
    float xval = (l < 12) ? __ldg(xg + (long long)trow0 * G4 + colg) : 0.f;

    for (int t = 0; t < LSEQ; t++) {
        int trow = dir ? (LSEQ - 1 - t) : t;
        float xnext = 0.f;
        if (l < 12 && t + 1 < LSEQ) {
            int trn = dir ? (LSEQ - 2 - t) : (t + 1);
            xnext = __ldg(xg + (long long)trn * G4 + colg);
        }
        int par = t & 1;
        int parn = par ^ 1;

        // matvec from parity buffer (step-t h, delivered by peers last step)
        float hk[12];
#pragma unroll
        for (int k = 0; k < 12; k++) hk[k] = h_buf[par][l + 32 * k];
        float a[12];
#pragma unroll
        for (int i = 0; i < 12; i++) a[i] = 0.f;
#pragma unroll
        for (int k = 0; k < 12; k++) {
            float h = hk[k];
#pragma unroll
            for (int i = 0; i < 12; i++) a[i] += W[i][k] * h;
        }
#pragma unroll
        for (int st = 16; st > 0; st >>= 1) {
#pragma unroll
            for (int i = 0; i < 12; i++) a[i] += __shfl_xor_sync(0xffffffffu, a[i], st);
        }
        if (l < 12) {
            float my = 0.f;
#pragma unroll
            for (int i = 0; i < 12; i++)
                if (l == i) my = a[i];
            gate_sh[q_h] = my + xval + bias_h;
        }
        __syncthreads();

        if (tid < 24) {
            float iv = sigf(gate_sh[tid]);
            float fv = sigf(gate_sh[24 + tid]);
            float gv = tanh_fast(gate_sh[48 + tid]);
            float ov = sigf(gate_sh[72 + tid]);
            cstate = fv * cstate + iv * gv;
            float hv = ov * tanh_fast(cstate);
            int hidx = cid * 24 + tid;
            g_tok[trow][dir * HID + hidx] = hv;
            unsigned laddr = smem_u32(&h_buf[parn][hidx]);
            unsigned mbn = parn ? mb1 : mb0;
#pragma unroll
            for (int p = 0; p < 16; p++) st_cluster_f32(laddr, p, hv);
#pragma unroll
            for (int p = 0; p < 16; p++) mbar_arrive_cluster(mbn, p);
        }

        // acquire-wait for all 384 arrivals of step t+1 data
        mbar_wait_parity_cluster(parn ? mb1 : mb0, (unsigned)((t >> 1) & 1));
        __syncthreads();

        xval = xnext;
    }
}

// ---------------- LSTM fallback: R6 global packed exchange ----------------
__global__ void __launch_bounds__(256, 1) lstm_kernel(const float* __restrict__ w_hh_f,
                                                      const float* __restrict__ b_f,
                                                      const float* __restrict__ w_hh_b,
                                                      const float* __restrict__ b_b) {
    int dir = blockIdx.x >> 5;
    int cid = blockIdx.x & 31;
    const float* whh = dir ? w_hh_b : w_hh_f;
    const float* bb = dir ? b_b : b_f;
    int tid = threadIdx.x;
    int w = tid >> 5, l = tid & 31;

    __shared__ float h_sh[HID];
    __shared__ float gate_sh[48];

    float W[6][12];
#pragma unroll
    for (int i = 0; i < 6; i++) {
        int q = w * 6 + i;
        int grow = (q / 12) * HID + cid * 12 + (q % 12);
#pragma unroll
        for (int k = 0; k < 12; k++) W[i][k] = whh[(long long)grow * HID + (l + 32 * k)];
    }
    int q_h = w * 6 + l;
    int gx = (l < 6) ? ((q_h / 12) * HID + cid * 12 + (q_h % 12)) : 0;
    float bias_h = (l < 6) ? bb[gx] : 0.f;
    const float* xg = &g_xg[dir][0][0];

    float cstate = 0.f;
    for (int i = tid; i < HID; i += 256) h_sh[i] = 0.f;
    __syncthreads();

    int trow0 = dir ? (LSEQ - 1) : 0;
    float xval = (l < 6) ? __ldg(xg + (long long)trow0 * G4 + gx) : 0.f;

    for (int t = 0; t < LSEQ; t++) {
        int trow = dir ? (LSEQ - 1 - t) : t;
        float xnext = 0.f;
        if (l < 6 && t + 1 < LSEQ) {
            int trn = dir ? (LSEQ - 2 - t) : (t + 1);
            xnext = __ldg(xg + (long long)trn * G4 + gx);
        }

        float hk[12];
#pragma unroll
        for (int k = 0; k < 12; k++) hk[k] = h_sh[l + 32 * k];
        float a0 = 0.f, a1 = 0.f, a2 = 0.f, a3 = 0.f, a4 = 0.f, a5 = 0.f;
#pragma unroll
        for (int k = 0; k < 12; k++) {
            float h = hk[k];
            a0 += W[0][k] * h;
            a1 += W[1][k] * h;
            a2 += W[2][k] * h;
            a3 += W[3][k] * h;
            a4 += W[4][k] * h;
            a5 += W[5][k] * h;
        }
#pragma unroll
        for (int st = 16; st > 0; st >>= 1) {
            a0 += __shfl_xor_sync(0xffffffffu, a0, st);
            a1 += __shfl_xor_sync(0xffffffffu, a1, st);
            a2 += __shfl_xor_sync(0xffffffffu, a2, st);
            a3 += __shfl_xor_sync(0xffffffffu, a3, st);
            a4 += __shfl_xor_sync(0xffffffffu, a4, st);
            a5 += __shfl_xor_sync(0xffffffffu, a5, st);
        }
        if (l < 6) {
            float my = (l == 0) ? a0 : (l == 1) ? a1 : (l == 2) ? a2
                      : (l == 3) ? a3 : (l == 4) ? a4 : a5;
            gate_sh[q_h] = my + xval + bias_h;
        }
        __syncthreads();

        int par = t & 1;
        unsigned tag = (unsigned)(t + 1);
        if (tid < 12) {
            float iv = sigf(gate_sh[tid]);
            float fv = sigf(gate_sh[12 + tid]);
            float gv = tanh_fast(gate_sh[24 + tid]);
            float ov = sigf(gate_sh[36 + tid]);
            cstate = fv * cstate + iv * gv;
            float hv = ov * tanh_fast(cstate);
            int hidx = cid * 12 + tid;
            unsigned long long pk = ((unsigned long long)tag << 32) |
                                    (unsigned)__float_as_int(hv);
            stvol64(&g_hpack[dir][par][hidx], pk);
            g_tok[trow][dir * HID + hidx] = hv;
        }

        const unsigned long long* hp = &g_hpack[dir][par][0];
        unsigned long long v1 = ldvol64(hp + tid);
        unsigned long long v2 = 0ULL;
        if (tid < 128) v2 = ldvol64(hp + tid + 256);
        while ((unsigned)(v1 >> 32) != tag) v1 = ldvol64(hp + tid);
        h_sh[tid] = __int_as_float((int)(unsigned)v1);
        if (tid < 128) {
            while ((unsigned)(v2 >> 32) != tag) v2 = ldvol64(hp + tid + 256);
            h_sh[tid + 256] = __int_as_float((int)(unsigned)v2);
        }
        __syncthreads();

        xval = xnext;
    }
}

// ---------------- 3-phase parallel scan over tok ----------------
__global__ void scan1_kernel() {
    int b = blockIdx.x;
    for (int d = threadIdx.x; d < 2 * HID; d += 256) {
        float s = 0.f;
        for (int r = 0; r < 128; r++) s += g_tok[b * 128 + r][d];
        g_csum[b][d] = s;
    }
}
__global__ void scan2_kernel() {
    int d = threadIdx.x;
    float run = 0.f;
    for (int b = 0; b < 32; b++) {
        float v = g_csum[b][d];
        g_csum[b][d] = run;
        run += v;
    }
}
__global__ void scan3_kernel() {
    int b = blockIdx.x;
    for (int d = threadIdx.x; d < 2 * HID; d += 256) {
        float run = g_csum[b][d];
        if (b == 0) g_prefix[0][d] = 0.f;
        for (int r = 0; r < 128; r++) {
            run += g_tok[b * 128 + r][d];
            g_prefix[b * 128 + r + 1][d] = run;
        }
    }
}

// ---------------- event embeddings ----------------
__global__ void event_kernel(const void* __restrict__ lab_ev) {
    int d = blockIdx.x * blockDim.x + threadIdx.x;
    int e = blockIdx.y;
    if (d >= 2 * HID) return;
    long long st = fetch_idx(lab_ev, 0, 2LL * e);
    long long en = fetch_idx(lab_ev, 0, 2LL * e + 1);
    g_evemb[e][d] = (g_prefix[en][d] - g_prefix[st][d]) / (float)(en - st);
}

// ---------------- fold W1 into [A|B|C] ----------------
__global__ void wprep_kernel(const float* __restrict__ w1) {
    int k = blockIdx.x * blockDim.x + threadIdx.x;
    int n = blockIdx.y;
    if (k >= K3) return;
    int seg = k / 768, kk = k - seg * 768;
    const float* r = w1 + (long long)n * 3072;
    float v;
    if (seg == 0) v = r[kk] + r[1536 + kk];
    else if (seg == 1) v = r[768 + kk] - r[1536 + kk];
    else v = r[2304 + kk];
    g_wp[n][k] = v;
}

// ---------------- scores + log-softmax + CE + loss ----------------
__global__ void scores_kernel(const float* __restrict__ w3, const float* __restrict__ b3,
                              const void* __restrict__ labt, float* __restrict__ out,
                              int loss_off) {
    __shared__ float w3s[4][256];
    __shared__ float ce_sh[8];
    int tid = threadIdx.x;
    int wp = tid >> 5, l = tid & 31;
    for (int i = tid; i < 1024; i += 256) w3s[i >> 8][i & 255] = w3[i];
    __syncthreads();

    int p = blockIdx.x * 8 + wp;
    const float* h2r = &g_h2[p][0];
    float hv[8];
#pragma unroll
    for (int k = 0; k < 8; k++) hv[k] = h2r[l + 32 * k];
    float s[4];
#pragma unroll
    for (int j = 0; j < 4; j++) {
        float t = 0.f;
#pragma unroll
        for (int k = 0; k < 8; k++) t += hv[k] * w3s[j][l + 32 * k];
        t += __shfl_xor_sync(0xffffffffu, t, 16);
        t += __shfl_xor_sync(0xffffffffu, t, 8);
        t += __shfl_xor_sync(0xffffffffu, t, 4);
        t += __shfl_xor_sync(0xffffffffu, t, 2);
        t += __shfl_xor_sync(0xffffffffu, t, 1);
        s[j] = t + b3[j];
    }
    if (l == 0) {
        float m = fmaxf(fmaxf(s[0], s[1]), fmaxf(s[2], s[3]));
        float se = expf(s[0] - m) + expf(s[1] - m) + expf(s[2] - m) + expf(s[3] - m);
        float lse = m + logf(se);
        long long y = fetch_idx(labt, 2, p);
        float sy = (y == 0) ? s[0] : (y == 1) ? s[1] : (y == 2) ? s[2] : s[3];
        float* o = out + loss_off + 4LL * p;
        o[0] = s[0]; o[1] = s[1]; o[2] = s[2]; o[3] = s[3];
        ce_sh[wp] = lse - sy;
    }
    __syncthreads();
    if (tid == 0 && loss_off) {
        float t = 0.f;
#pragma unroll
        for (int i = 0; i < 8; i++) t += ce_sh[i];
        atomicAdd(out, t);
    }
}

// ---------------- launch ----------------
extern "C" void kernel_launch(void* const* d_in, const int* in_sizes, int n_in,
                              void* d_out, int out_size) {
    const float* tokemb = (const float*)d_in[0];
    const float* w_ih_f = (const float*)d_in[1];
    const float* w_hh_f = (const float*)d_in[2];
    const float* b_f = (const float*)d_in[3];
    const float* w_ih_b = (const float*)d_in[4];
    const float* w_hh_b = (const float*)d_in[5];
    const float* b_b = (const float*)d_in[6];
    const float* w1 = (const float*)d_in[7];
    const float* b1 = (const float*)d_in[8];
    const float* w2 = (const float*)d_in[9];
    const float* b2 = (const float*)d_in[10];
    const float* w3 = (const float*)d_in[11];
    const float* b3 = (const float*)d_in[12];
    const void* lab_ev = d_in[13];
    const void* pairs = d_in[14];
    const void* labt = d_in[15];
    float* out = (float*)d_out;
    int loss_off = (out_size > 4 * PN_) ? 1 : 0;

    void *p_xg, *p_h1, *p_h2;
    cudaGetSymbolAddress(&p_xg, g_xg);
    cudaGetSymbolAddress(&p_h1, g_h1);
    cudaGetSymbolAddress(&p_h2, g_h2);
    float* xg0 = (float*)p_xg;
    float* xg1 = xg0 + (long long)LSEQ * G4;

    detect_kernel<<<1, 1>>>(lab_ev, pairs, labt);
    init_kernel<<<32, 256>>>(out, loss_off);

    sgemm_nt<<<dim3(G4 / BN, LSEQ / BM), 256>>>(tokemb, w_ih_f, xg0, LSEQ, G4, DIM, nullptr, 0);
    sgemm_nt<<<dim3(G4 / BN, LSEQ / BM), 256>>>(tokemb, w_ih_b, xg1, LSEQ, G4, DIM, nullptr, 0);

    // recurrence: cluster-16 + mbarrier exchange if supported, else fallback
    {
        cudaFuncSetAttribute(lstm_cluster_kernel,
                             cudaFuncAttributeNonPortableClusterSizeAllowed, 1);
        cudaLaunchConfig_t cfg = {};
        cfg.gridDim = dim3(32, 1, 1);
        cfg.blockDim = dim3(256, 1, 1);
        cfg.dynamicSmemBytes = 0;
        cudaLaunchAttribute at[1];
        at[0].id = cudaLaunchAttributeClusterDimension;
        at[0].val.clusterDim.x = 16;
        at[0].val.clusterDim.y = 1;
        at[0].val.clusterDim.z = 1;
        cfg.attrs = at;
        cfg.numAttrs = 1;
        int nclus = 0;
        cudaError_t qe = cudaOccupancyMaxActiveClusters(&nclus, lstm_cluster_kernel, &cfg);
        if (qe == cudaSuccess && nclus >= 2) {
            cudaLaunchKernelEx(&cfg, lstm_cluster_kernel, w_hh_f, b_f, w_hh_b, b_b);
        } else {
            cudaGetLastError();  // clear any sticky query error
            lstm_kernel<<<64, 256>>>(w_hh_f, b_f, w_hh_b, b_b);
        }
    }

    scan1_kernel<<<32, 256>>>();
    scan2_kernel<<<1, 2 * HID>>>();
    scan3_kernel<<<32, 256>>>();
    event_kernel<<<dim3(3, EN_), 256>>>(lab_ev);

    wprep_kernel<<<dim3(9, DIM), 256>>>(w1);
    tgemm_feat<<<dim3(DIM / 128, PN_ / 128), 256>>>(pairs, (float*)p_h1, b1);
    tgemm_nt<<<dim3(256 / 128, PN_ / 128), 256>>>((const float*)p_h1, w2, (float*)p_h2,
                                                  PN_, 256, DIM, b2, 1);

    scores_kernel<<<PN_ / 8, 256>>>(w3, b3, labt, out, loss_off);
}

// round 10
// speedup vs baseline: 1.8876x; 1.0578x over previous
#include <cuda_runtime.h>
#include <cstdint>

#define LSEQ 4096
#define DIM 768
#define HID 384
#define G4 1536
#define EN_ 32768
#define PN_ 32768
#define K3 2304   // 3*768 folded-K for pair MLP

// ---------------- scratch (device globals; no allocation allowed) ----------------
__device__ float g_xg[2][LSEQ][G4];
__device__ float g_tok[LSEQ][2 * HID];
__device__ float g_prefix[LSEQ + 1][2 * HID];
__device__ float g_csum[32][2 * HID];
__device__ float g_evemb[EN_][2 * HID];
__device__ float g_wp[DIM][K3];
__device__ float g_h1[PN_][DIM];
__device__ float g_h2[PN_][256];
__device__ unsigned long long g_hpack[2][2][HID];  // fallback path: (tag<<32)|f32
__device__ int g_is64[3];

// ---------------- helpers ----------------
__device__ __forceinline__ long long fetch_idx(const void* p, int which, long long i) {
    if (g_is64[which]) return ((const long long*)p)[i];
    return (long long)((const int*)p)[i];
}
__device__ __forceinline__ float sigf(float x) { return 1.f / (1.f + __expf(-x)); }
__device__ __forceinline__ float tanh_fast(float x) {
    x = fminf(15.f, fmaxf(-15.f, x));
    float e = __expf(-2.f * x);
    return (1.f - e) / (1.f + e);
}
__device__ __forceinline__ unsigned long long ldvol64(const unsigned long long* p) {
    unsigned long long v;
    asm volatile("ld.volatile.global.b64 %0, [%1];" : "=l"(v) : "l"(p));
    return v;
}
__device__ __forceinline__ void stvol64(unsigned long long* p, unsigned long long v) {
    asm volatile("st.volatile.global.b64 [%0], %1;" :: "l"(p), "l"(v));
}
__device__ __forceinline__ unsigned f2tf32(float f) {
    unsigned r;
    asm("cvt.rna.tf32.f32 %0, %1;" : "=r"(r) : "f"(f));
    return r;
}
__device__ __forceinline__ unsigned smem_u32(const void* p) {
    return (unsigned)__cvta_generic_to_shared(p);
}
__device__ __forceinline__ void st_cluster_f32(unsigned laddr, int rank, float v) {
    unsigned r;
    asm volatile("mapa.shared::cluster.u32 %0, %1, %2;" : "=r"(r) : "r"(laddr), "r"(rank));
    asm volatile("st.shared::cluster.f32 [%0], %1;" :: "r"(r), "f"(v));
}
__device__ __forceinline__ void st_cluster_v4(unsigned laddr, int rank, float4 v) {
    unsigned r;
    asm volatile("mapa.shared::cluster.u32 %0, %1, %2;" : "=r"(r) : "r"(laddr), "r"(rank));
    asm volatile("st.shared::cluster.v4.f32 [%0], {%1,%2,%3,%4};"
                 :: "r"(r), "f"(v.x), "f"(v.y), "f"(v.z), "f"(v.w));
}
// remote arrive: release-orders prior DSMEM stores (sync-then-elect pattern)
__device__ __forceinline__ void mbar_arrive_cluster(unsigned local_mbar, int rank) {
    asm volatile(
        "{\n\t"
        ".reg .b32 ra;\n\t"
        "mapa.shared::cluster.u32 ra, %0, %1;\n\t"
        "mbarrier.arrive.shared::cluster.b64 _, [ra];\n\t"
        "}"
        :: "r"(local_mbar), "r"(rank) : "memory");
}
__device__ __forceinline__ void mbar_init(unsigned mbar, unsigned cnt) {
    asm volatile("mbarrier.init.shared.b64 [%0], %1;" :: "r"(mbar), "r"(cnt) : "memory");
}
__device__ __forceinline__ void mbar_wait_parity_cluster(unsigned mbar, unsigned ph) {
    unsigned done;
    asm volatile(
        "{\n\t"
        ".reg .pred p;\n\t"
        "mbarrier.try_wait.parity.acquire.cluster.shared::cta.b64 p, [%1], %2;\n\t"
        "selp.b32 %0, 1, 0, p;\n\t"
        "}"
        : "=r"(done) : "r"(mbar), "r"(ph) : "memory");
    while (!done) {
        asm volatile(
            "{\n\t"
            ".reg .pred p;\n\t"
            "mbarrier.try_wait.parity.acquire.cluster.shared::cta.b64 p, [%1], %2, 0x989680;\n\t"
            "selp.b32 %0, 1, 0, p;\n\t"
            "}"
            : "=r"(done) : "r"(mbar), "r"(ph) : "memory");
    }
}

// ---------------- dtype detection + init ----------------
__global__ void detect_kernel(const void* lab_ev, const void* pairs, const void* labt) {
    if (threadIdx.x == 0) {
        const int* a = (const int*)lab_ev;
        int nz = 0;
        for (int i = 0; i < 64; i++) nz |= a[2 * i + 1];
        g_is64[0] = (nz == 0);
        const int* b = (const int*)pairs;
        nz = 0;
        for (int i = 0; i < 64; i++) nz |= b[2 * i + 1];
        g_is64[1] = (nz == 0);
        const int* c = (const int*)labt;
        nz = 0;
        for (int i = 0; i < 64; i++) nz |= c[2 * i + 1];
        g_is64[2] = (nz == 0);
    }
}

__global__ void init_kernel(float* out, int loss_off) {
    int i = blockIdx.x * blockDim.x + threadIdx.x;
    if (i < 2 * 2 * HID) ((unsigned long long*)g_hpack)[i] = 0ULL;
    if (i == 0 && loss_off) out[0] = 0.f;
}

// ---------------- fp32 SIMT GEMM (xgate; exact) ----------------
#define BM 128
#define BN 128
#define BKG 16
__global__ void __launch_bounds__(256) sgemm_nt(const float* __restrict__ A,
                                                const float* __restrict__ B,
                                                float* __restrict__ C,
                                                int M, int N, int K,
                                                const float* __restrict__ bias, int relu) {
    __shared__ float As[BKG][BM];
    __shared__ float Bs[BKG][BN];
    int bm = blockIdx.y, bn = blockIdx.x;
    int tid = threadIdx.x;
    int tx = tid & 15, ty = tid >> 4;
    const float* Ab = A + (long long)bm * BM * K;
    const float* Bb = B + (long long)bn * BN * K;

    float acc[8][8];
#pragma unroll
    for (int i = 0; i < 8; i++)
#pragma unroll
        for (int j = 0; j < 8; j++) acc[i][j] = 0.f;

    float4 pa[2], pb[2];
#pragma unroll
    for (int b = 0; b < 2; b++) {
        int f = tid + b * 256;
        int row = f >> 2, c4 = f & 3;
        pa[b] = *(const float4*)(Ab + (long long)row * K + c4 * 4);
        pb[b] = *(const float4*)(Bb + (long long)row * K + c4 * 4);
    }

    for (int k0 = 0; k0 < K; k0 += BKG) {
#pragma unroll
        for (int b = 0; b < 2; b++) {
            int f = tid + b * 256;
            int row = f >> 2, c4 = f & 3;
            As[c4 * 4 + 0][row] = pa[b].x;
            As[c4 * 4 + 1][row] = pa[b].y;
            As[c4 * 4 + 2][row] = pa[b].z;
            As[c4 * 4 + 3][row] = pa[b].w;
            Bs[c4 * 4 + 0][row] = pb[b].x;
            Bs[c4 * 4 + 1][row] = pb[b].y;
            Bs[c4 * 4 + 2][row] = pb[b].z;
            Bs[c4 * 4 + 3][row] = pb[b].w;
        }
        __syncthreads();
        if (k0 + BKG < K) {
#pragma unroll
            for (int b = 0; b < 2; b++) {
                int f = tid + b * 256;
                int row = f >> 2, c4 = f & 3;
                pa[b] = *(const float4*)(Ab + (long long)row * K + (k0 + BKG) + c4 * 4);
                pb[b] = *(const float4*)(Bb + (long long)row * K + (k0 + BKG) + c4 * 4);
            }
        }
#pragma unroll
        for (int kk = 0; kk < BKG; kk++) {
            float a[8], bq[8];
            *(float4*)&a[0] = *(const float4*)&As[kk][ty * 8];
            *(float4*)&a[4] = *(const float4*)&As[kk][ty * 8 + 4];
            *(float4*)&bq[0] = *(const float4*)&Bs[kk][tx * 8];
            *(float4*)&bq[4] = *(const float4*)&Bs[kk][tx * 8 + 4];
#pragma unroll
            for (int i = 0; i < 8; i++)
#pragma unroll
                for (int j = 0; j < 8; j++) acc[i][j] += a[i] * bq[j];
        }
        __syncthreads();
    }

#pragma unroll
    for (int i = 0; i < 8; i++) {
        long long m = (long long)bm * BM + ty * 8 + i;
#pragma unroll
        for (int j = 0; j < 8; j += 4) {
            int n = bn * BN + tx * 8 + j;
            float4 v;
            v.x = acc[i][j + 0];
            v.y = acc[i][j + 1];
            v.z = acc[i][j + 2];
            v.w = acc[i][j + 3];
            if (bias) {
                v.x += bias[n + 0];
                v.y += bias[n + 1];
                v.z += bias[n + 2];
                v.w += bias[n + 3];
            }
            if (relu) {
                v.x = fmaxf(v.x, 0.f);
                v.y = fmaxf(v.y, 0.f);
                v.z = fmaxf(v.z, 0.f);
                v.w = fmaxf(v.w, 0.f);
            }
            *(float4*)(C + m * N + n) = v;
        }
    }
}

// ---------------- tf32 tensor-core GEMM (round-2 known-good layout) ----------------
#define TPAD 36
__global__ void __launch_bounds__(256) tgemm_nt(const float* __restrict__ A,
                                                const float* __restrict__ B,
                                                float* __restrict__ C,
                                                int M, int N, int K,
                                                const float* __restrict__ bias, int relu) {
    __shared__ unsigned As[128 * TPAD];
    __shared__ unsigned Bs[128 * TPAD];
    int bm = blockIdx.y, bn = blockIdx.x;
    int tid = threadIdx.x;
    int wid = tid >> 5, l = tid & 31;
    int wm = wid & 3, wn = wid >> 2;
    int gr = l >> 2, gc = l & 3;
    const float* Ab = A + (long long)bm * 128 * K;
    const float* Bb = B + (long long)bn * 128 * K;

    float acc[2][8][4];
#pragma unroll
    for (int mi = 0; mi < 2; mi++)
#pragma unroll
        for (int ni = 0; ni < 8; ni++)
#pragma unroll
            for (int c = 0; c < 4; c++) acc[mi][ni][c] = 0.f;

    int row[4], qk[4];
    float4 ra[4], rb[4];
#pragma unroll
    for (int i = 0; i < 4; i++) {
        int idx = tid + i * 256;
        row[i] = idx >> 3;
        qk[i] = idx & 7;
        ra[i] = *(const float4*)(Ab + (long long)row[i] * K + qk[i] * 4);
        rb[i] = *(const float4*)(Bb + (long long)row[i] * K + qk[i] * 4);
    }

    for (int k0 = 0; k0 < K; k0 += 32) {
#pragma unroll
        for (int i = 0; i < 4; i++) {
            int base = row[i] * TPAD + qk[i] * 4;
            As[base + 0] = f2tf32(ra[i].x);
            As[base + 1] = f2tf32(ra[i].y);
            As[base + 2] = f2tf32(ra[i].z);
            As[base + 3] = f2tf32(ra[i].w);
            Bs[base + 0] = f2tf32(rb[i].x);
            Bs[base + 1] = f2tf32(rb[i].y);
            Bs[base + 2] = f2tf32(rb[i].z);
            Bs[base + 3] = f2tf32(rb[i].w);
        }
        __syncthreads();
        if (k0 + 32 < K) {
#pragma unroll
            for (int i = 0; i < 4; i++) {
                ra[i] = *(const float4*)(Ab + (long long)row[i] * K + (k0 + 32) + qk[i] * 4);
                rb[i] = *(const float4*)(Bb + (long long)row[i] * K + (k0 + 32) + qk[i] * 4);
            }
        }
#pragma unroll
        for (int ks = 0; ks < 4; ks++) {
            unsigned a[2][4];
#pragma unroll
            for (int mi = 0; mi < 2; mi++) {
                int baseA = (wm * 32 + mi * 16 + gr) * TPAD + ks * 8 + gc;
                a[mi][0] = As[baseA];
                a[mi][1] = As[baseA + 8 * TPAD];
                a[mi][2] = As[baseA + 4];
                a[mi][3] = As[baseA + 8 * TPAD + 4];
            }
#pragma unroll
            for (int ni = 0; ni < 8; ni++) {
                int baseB = (wn * 64 + ni * 8 + gr) * TPAD + ks * 8 + gc;
                unsigned b0 = Bs[baseB];
                unsigned b1 = Bs[baseB + 4];
#pragma unroll
                for (int mi = 0; mi < 2; mi++) {
                    asm volatile(
                        "mma.sync.aligned.m16n8k8.row.col.f32.tf32.tf32.f32 "
                        "{%0,%1,%2,%3}, {%4,%5,%6,%7}, {%8,%9}, {%0,%1,%2,%3};\n"
                        : "+f"(acc[mi][ni][0]), "+f"(acc[mi][ni][1]),
                          "+f"(acc[mi][ni][2]), "+f"(acc[mi][ni][3])
                        : "r"(a[mi][0]), "r"(a[mi][1]), "r"(a[mi][2]), "r"(a[mi][3]),
                          "r"(b0), "r"(b1));
                }
            }
        }
        __syncthreads();
    }

#pragma unroll
    for (int mi = 0; mi < 2; mi++) {
#pragma unroll
        for (int ni = 0; ni < 8; ni++) {
            int rowc = bm * 128 + wm * 32 + mi * 16 + gr;
            int colc = bn * 128 + wn * 64 + ni * 8 + 2 * gc;
            float b0v = bias ? bias[colc] : 0.f;
            float b1v = bias ? bias[colc + 1] : 0.f;
            float2 v0, v1;
            v0.x = acc[mi][ni][0] + b0v;
            v0.y = acc[mi][ni][1] + b1v;
            v1.x = acc[mi][ni][2] + b0v;
            v1.y = acc[mi][ni][3] + b1v;
            if (relu) {
                v0.x = fmaxf(v0.x, 0.f);
                v0.y = fmaxf(v0.y, 0.f);
                v1.x = fmaxf(v1.x, 0.f);
                v1.y = fmaxf(v1.y, 0.f);
            }
            *(float2*)(C + (long long)rowc * N + colc) = v0;
            *(float2*)(C + (long long)(rowc + 8) * N + colc) = v1;
        }
    }
}

// ---------------- fused feat+GEMM1 (unchanged) ----------------
__device__ __forceinline__ float4 feat_lda(const int2* pr_sh, int lrow, int k) {
    int seg = k / 768, kk = k - seg * 768;
    int2 pr = pr_sh[lrow];
    if (seg == 0) return *(const float4*)&g_evemb[pr.x][kk];
    if (seg == 1) return *(const float4*)&g_evemb[pr.y][kk];
    float4 a = *(const float4*)&g_evemb[pr.x][kk];
    float4 b = *(const float4*)&g_evemb[pr.y][kk];
    return make_float4(a.x * b.x, a.y * b.y, a.z * b.z, a.w * b.w);
}

__global__ void __launch_bounds__(256) tgemm_feat(const void* __restrict__ pairs,
                                                  float* __restrict__ C,
                                                  const float* __restrict__ bias) {
    const int N = DIM, K = K3;
    __shared__ unsigned As[128 * TPAD];
    __shared__ unsigned Bs[128 * TPAD];
    __shared__ int2 pr_sh[128];
    int bm = blockIdx.y, bn = blockIdx.x;
    int tid = threadIdx.x;
    int wid = tid >> 5, l = tid & 31;
    int wm = wid & 3, wn = wid >> 2;
    int gr = l >> 2, gc = l & 3;
    const float* Bb = &g_wp[bn * 128][0];

    if (tid < 128) {
        long long p = (long long)bm * 128 + tid;
        pr_sh[tid] = make_int2((int)fetch_idx(pairs, 1, 2 * p),
                               (int)fetch_idx(pairs, 1, 2 * p + 1));
    }
    __syncthreads();

    float acc[2][8][4];
#pragma unroll
    for (int mi = 0; mi < 2; mi++)
#pragma unroll
        for (int ni = 0; ni < 8; ni++)
#pragma unroll
            for (int c = 0; c < 4; c++) acc[mi][ni][c] = 0.f;

    int row[4], qk[4];
    float4 ra[4], rb[4];
#pragma unroll
    for (int i = 0; i < 4; i++) {
        int idx = tid + i * 256;
        row[i] = idx >> 3;
        qk[i] = idx & 7;
        ra[i] = feat_lda(pr_sh, row[i], qk[i] * 4);
        rb[i] = *(const float4*)(Bb + (long long)row[i] * K + qk[i] * 4);
    }

    for (int k0 = 0; k0 < K; k0 += 32) {
#pragma unroll
        for (int i = 0; i < 4; i++) {
            int base = row[i] * TPAD + qk[i] * 4;
            As[base + 0] = f2tf32(ra[i].x);
            As[base + 1] = f2tf32(ra[i].y);
            As[base + 2] = f2tf32(ra[i].z);
            As[base + 3] = f2tf32(ra[i].w);
            Bs[base + 0] = f2tf32(rb[i].x);
            Bs[base + 1] = f2tf32(rb[i].y);
            Bs[base + 2] = f2tf32(rb[i].z);
            Bs[base + 3] = f2tf32(rb[i].w);
        }
        __syncthreads();
        if (k0 + 32 < K) {
#pragma unroll
            for (int i = 0; i < 4; i++) {
                ra[i] = feat_lda(pr_sh, row[i], (k0 + 32) + qk[i] * 4);
                rb[i] = *(const float4*)(Bb + (long long)row[i] * K + (k0 + 32) + qk[i] * 4);
            }
        }
#pragma unroll
        for (int ks = 0; ks < 4; ks++) {
            unsigned a[2][4];
#pragma unroll
            for (int mi = 0; mi < 2; mi++) {
                int baseA = (wm * 32 + mi * 16 + gr) * TPAD + ks * 8 + gc;
                a[mi][0] = As[baseA];
                a[mi][1] = As[baseA + 8 * TPAD];
                a[mi][2] = As[baseA + 4];
                a[mi][3] = As[baseA + 8 * TPAD + 4];
            }
#pragma unroll
            for (int ni = 0; ni < 8; ni++) {
                int baseB = (wn * 64 + ni * 8 + gr) * TPAD + ks * 8 + gc;
                unsigned b0 = Bs[baseB];
                unsigned b1 = Bs[baseB + 4];
#pragma unroll
                for (int mi = 0; mi < 2; mi++) {
                    asm volatile(
                        "mma.sync.aligned.m16n8k8.row.col.f32.tf32.tf32.f32 "
                        "{%0,%1,%2,%3}, {%4,%5,%6,%7}, {%8,%9}, {%0,%1,%2,%3};\n"
                        : "+f"(acc[mi][ni][0]), "+f"(acc[mi][ni][1]),
                          "+f"(acc[mi][ni][2]), "+f"(acc[mi][ni][3])
                        : "r"(a[mi][0]), "r"(a[mi][1]), "r"(a[mi][2]), "r"(a[mi][3]),
                          "r"(b0), "r"(b1));
                }
            }
        }
        __syncthreads();
    }

#pragma unroll
    for (int mi = 0; mi < 2; mi++) {
#pragma unroll
        for (int ni = 0; ni < 8; ni++) {
            int rowc = bm * 128 + wm * 32 + mi * 16 + gr;
            int colc = bn * 128 + wn * 64 + ni * 8 + 2 * gc;
            float b0v = bias[colc];
            float b1v = bias[colc + 1];
            float2 v0, v1;
            v0.x = fmaxf(acc[mi][ni][0] + b0v, 0.f);
            v0.y = fmaxf(acc[mi][ni][1] + b1v, 0.f);
            v1.x = fmaxf(acc[mi][ni][2] + b0v, 0.f);
            v1.y = fmaxf(acc[mi][ni][3] + b1v, 0.f);
            *(float2*)(C + (long long)rowc * N + colc) = v0;
            *(float2*)(C + (long long)(rowc + 8) * N + colc) = v1;
        }
    }
}

// ---------------- LSTM: cluster-16 DSMEM + mbarrier, lean reduction/push ----------
// Grid 32, cluster {16,1,1}. CTA owns 24 h rows (96 gate rows; W=144 regs/thread).
// Step t: matvec(h_buf[t&1]) -> fold-reduce (18 SHFL) -> act(24 thr, adds x+bias)
// -> stage smem -> 6 threads push float4 to 16 peers -> elected lane0 sends 16
// arrives (mbar count 16) -> acquire-wait.
__global__ void __launch_bounds__(256, 1) lstm_cluster_kernel(const float* __restrict__ w_hh_f,
                                                              const float* __restrict__ b_f,
                                                              const float* __restrict__ w_hh_b,
                                                              const float* __restrict__ b_b) {
    int bid = blockIdx.x;
    int dir = bid >> 4;
    int cid = bid & 15;
    const float* whh = dir ? w_hh_b : w_hh_f;
    const float* bb = dir ? b_b : b_f;
    int tid = threadIdx.x;
    int w = tid >> 5, l = tid & 31;

    __shared__ float h_buf[2][HID];
    __shared__ float gate_sh[96];
    __shared__ __align__(16) float stage_sh[24];
    __shared__ __align__(8) unsigned long long mb[2];

    float W[12][12];
#pragma unroll
    for (int i = 0; i < 12; i++) {
        int q = w * 12 + i;
        int grow = (q / 24) * HID + cid * 24 + (q % 24);
#pragma unroll
        for (int k = 0; k < 12; k++) W[i][k] = whh[(long long)grow * HID + (l + 32 * k)];
    }
    // activation-thread setup (tid < 24): 4 gate rows i/f/g/o for h index hidx24
    int hidx24 = cid * 24 + tid;
    float bias4[4] = {0.f, 0.f, 0.f, 0.f};
    if (tid < 24) {
#pragma unroll
        for (int g = 0; g < 4; g++) bias4[g] = bb[g * HID + hidx24];
    }
    const float* xg = &g_xg[dir][0][0];

    unsigned mb0 = smem_u32(&mb[0]);
    unsigned mb1 = smem_u32(&mb[1]);
    if (tid == 0) {
        mbar_init(mb0, 16);
        mbar_init(mb1, 16);
    }
    for (int i = tid; i < 2 * HID; i += 256) ((float*)h_buf)[i] = 0.f;
    __syncthreads();
    // all CTAs' buffers zeroed + mbarriers initialized before any peer traffic
    asm volatile("barrier.cluster.arrive.aligned;" ::: "memory");
    asm volatile("barrier.cluster.wait.aligned;" ::: "memory");

    float cstate = 0.f;
    float xv[4] = {0.f, 0.f, 0.f, 0.f};
    if (tid < 24) {
        int trow0 = dir ? (LSEQ - 1) : 0;
#pragma unroll
        for (int g = 0; g < 4; g++)
            xv[g] = __ldg(xg + (long long)trow0 * G4 + g * HID + hidx24);
    }

    for (int t = 0; t < LSEQ; t++) {
        int trow = dir ? (LSEQ - 1 - t) : t;
        float xn[4] = {0.f, 0.f, 0.f, 0.f};
        if (tid < 24 && t + 1 < LSEQ) {
            int trn = dir ? (LSEQ - 2 - t) : (t + 1);
#pragma unroll
            for (int g = 0; g < 4; g++)
                xn[g] = __ldg(xg + (long long)trn * G4 + g * HID + hidx24);
        }
        int par = t & 1;
        int parn = par ^ 1;

        // matvec from parity buffer
        float hk[12];
#pragma unroll
        for (int k = 0; k < 12; k++) hk[k] = h_buf[par][l + 32 * k];
        float a[12];
#pragma unroll
        for (int i = 0; i < 12; i++) a[i] = 0.f;
#pragma unroll
        for (int k = 0; k < 12; k++) {
            float h = hk[k];
#pragma unroll
            for (int i = 0; i < 12; i++) a[i] += W[i][k] * h;
        }

        // fold reduction: 12 -> 6 (xor16) -> 3 (xor8) -> butterfly(4,2,1)
        float b6[6];
        bool hi4 = (l & 16) != 0;
#pragma unroll
        for (int i = 0; i < 6; i++) {
            float x = hi4 ? a[i + 6] : a[i];
            float y = hi4 ? a[i] : a[i + 6];
            b6[i] = x + __shfl_xor_sync(0xffffffffu, y, 16);
        }
        float c3[3];
        bool hi3 = (l & 8) != 0;
#pragma unroll
        for (int i = 0; i < 3; i++) {
            float x = hi3 ? b6[i + 3] : b6[i];
            float y = hi3 ? b6[i] : b6[i + 3];
            c3[i] = x + __shfl_xor_sync(0xffffffffu, y, 8);
        }
#pragma unroll
        for (int st = 4; st > 0; st >>= 1) {
#pragma unroll
            for (int i = 0; i < 3; i++) c3[i] += __shfl_xor_sync(0xffffffffu, c3[i], st);
        }
        // lane l in {0,8,16,24} holds rows r..r+2, r = 6*bit4 + 3*bit3
        if ((l & 7) == 0) {
            int r = ((l >> 4) & 1) * 6 + ((l >> 3) & 1) * 3;
            gate_sh[w * 12 + r + 0] = c3[0];
            gate_sh[w * 12 + r + 1] = c3[1];
            gate_sh[w * 12 + r + 2] = c3[2];
        }
        __syncthreads();

        unsigned mbn = parn ? mb1 : mb0;
        if (tid < 24) {
            float iv = sigf(gate_sh[tid] + xv[0] + bias4[0]);
            float fv = sigf(gate_sh[24 + tid] + xv[1] + bias4[1]);
            float gv = tanh_fast(gate_sh[48 + tid] + xv[2] + bias4[2]);
            float ov = sigf(gate_sh[72 + tid] + xv[3] + bias4[3]);
            cstate = fv * cstate + iv * gv;
            float hv = ov * tanh_fast(cstate);
            g_tok[trow][dir * HID + hidx24] = hv;
            stage_sh[tid] = hv;
        }
        __syncwarp();
        if (tid < 6) {
            float4 v = *(const float4*)&stage_sh[tid * 4];
            unsigned laddr = smem_u32(&h_buf[parn][cid * 24 + tid * 4]);
#pragma unroll
            for (int p = 0; p < 16; p++) st_cluster_v4(laddr, p, v);
        }
        __syncwarp();
        if (tid == 0) {
#pragma unroll
            for (int p = 0; p < 16; p++) mbar_arrive_cluster(mbn, p);
        }

        // acquire-wait for 16 arrivals of step t+1 data
        mbar_wait_parity_cluster(mbn, (unsigned)((t >> 1) & 1));

#pragma unroll
        for (int g = 0; g < 4; g++) xv[g] = xn[g];
    }
}

// ---------------- LSTM fallback: R6 global packed exchange ----------------
__global__ void __launch_bounds__(256, 1) lstm_kernel(const float* __restrict__ w_hh_f,
                                                      const float* __restrict__ b_f,
                                                      const float* __restrict__ w_hh_b,
                                                      const float* __restrict__ b_b) {
    int dir = blockIdx.x >> 5;
    int cid = blockIdx.x & 31;
    const float* whh = dir ? w_hh_b : w_hh_f;
    const float* bb = dir ? b_b : b_f;
    int tid = threadIdx.x;
    int w = tid >> 5, l = tid & 31;

    __shared__ float h_sh[HID];
    __shared__ float gate_sh[48];

    float W[6][12];
#pragma unroll
    for (int i = 0; i < 6; i++) {
        int q = w * 6 + i;
        int grow = (q / 12) * HID + cid * 12 + (q % 12);
#pragma unroll
        for (int k = 0; k < 12; k++) W[i][k] = whh[(long long)grow * HID + (l + 32 * k)];
    }
    int q_h = w * 6 + l;
    int gx = (l < 6) ? ((q_h / 12) * HID + cid * 12 + (q_h % 12)) : 0;
    float bias_h = (l < 6) ? bb[gx] : 0.f;
    const float* xg = &g_xg[dir][0][0];

    float cstate = 0.f;
    for (int i = tid; i < HID; i += 256) h_sh[i] = 0.f;
    __syncthreads();

    int trow0 = dir ? (LSEQ - 1) : 0;
    float xval = (l < 6) ? __ldg(xg + (long long)trow0 * G4 + gx) : 0.f;

    for (int t = 0; t < LSEQ; t++) {
        int trow = dir ? (LSEQ - 1 - t) : t;
        float xnext = 0.f;
        if (l < 6 && t + 1 < LSEQ) {
            int trn = dir ? (LSEQ - 2 - t) : (t + 1);
            xnext = __ldg(xg + (long long)trn * G4 + gx);
        }

        float hk[12];
#pragma unroll
        for (int k = 0; k < 12; k++) hk[k] = h_sh[l + 32 * k];
        float a0 = 0.f, a1 = 0.f, a2 = 0.f, a3 = 0.f, a4 = 0.f, a5 = 0.f;
#pragma unroll
        for (int k = 0; k < 12; k++) {
            float h = hk[k];
            a0 += W[0][k] * h;
            a1 += W[1][k] * h;
            a2 += W[2][k] * h;
            a3 += W[3][k] * h;
            a4 += W[4][k] * h;
            a5 += W[5][k] * h;
        }
#pragma unroll
        for (int st = 16; st > 0; st >>= 1) {
            a0 += __shfl_xor_sync(0xffffffffu, a0, st);
            a1 += __shfl_xor_sync(0xffffffffu, a1, st);
            a2 += __shfl_xor_sync(0xffffffffu, a2, st);
            a3 += __shfl_xor_sync(0xffffffffu, a3, st);
            a4 += __shfl_xor_sync(0xffffffffu, a4, st);
            a5 += __shfl_xor_sync(0xffffffffu, a5, st);
        }
        if (l < 6) {
            float my = (l == 0) ? a0 : (l == 1) ? a1 : (l == 2) ? a2
                      : (l == 3) ? a3 : (l == 4) ? a4 : a5;
            gate_sh[q_h] = my + xval + bias_h;
        }
        __syncthreads();

        int par = t & 1;
        unsigned tag = (unsigned)(t + 1);
        if (tid < 12) {
            float iv = sigf(gate_sh[tid]);
            float fv = sigf(gate_sh[12 + tid]);
            float gv = tanh_fast(gate_sh[24 + tid]);
            float ov = sigf(gate_sh[36 + tid]);
            cstate = fv * cstate + iv * gv;
            float hv = ov * tanh_fast(cstate);
            int hidx = cid * 12 + tid;
            unsigned long long pk = ((unsigned long long)tag << 32) |
                                    (unsigned)__float_as_int(hv);
            stvol64(&g_hpack[dir][par][hidx], pk);
            g_tok[trow][dir * HID + hidx] = hv;
        }

        const unsigned long long* hp = &g_hpack[dir][par][0];
        unsigned long long v1 = ldvol64(hp + tid);
        unsigned long long v2 = 0ULL;
        if (tid < 128) v2 = ldvol64(hp + tid + 256);
        while ((unsigned)(v1 >> 32) != tag) v1 = ldvol64(hp + tid);
        h_sh[tid] = __int_as_float((int)(unsigned)v1);
        if (tid < 128) {
            while ((unsigned)(v2 >> 32) != tag) v2 = ldvol64(hp + tid + 256);
            h_sh[tid + 256] = __int_as_float((int)(unsigned)v2);
        }
        __syncthreads();

        xval = xnext;
    }
}

// ---------------- 3-phase parallel scan over tok ----------------
__global__ void scan1_kernel() {
    int b = blockIdx.x;
    for (int d = threadIdx.x; d < 2 * HID; d += 256) {
        float s = 0.f;
        for (int r = 0; r < 128; r++) s += g_tok[b * 128 + r][d];
        g_csum[b][d] = s;
    }
}
__global__ void scan2_kernel() {
    int d = threadIdx.x;
    float run = 0.f;
    for (int b = 0; b < 32; b++) {
        float v = g_csum[b][d];
        g_csum[b][d] = run;
        run += v;
    }
}
__global__ void scan3_kernel() {
    int b = blockIdx.x;
    for (int d = threadIdx.x; d < 2 * HID; d += 256) {
        float run = g_csum[b][d];
        if (b == 0) g_prefix[0][d] = 0.f;
        for (int r = 0; r < 128; r++) {
            run += g_tok[b * 128 + r][d];
            g_prefix[b * 128 + r + 1][d] = run;
        }
    }
}

// ---------------- event embeddings ----------------
__global__ void event_kernel(const void* __restrict__ lab_ev) {
    int d = blockIdx.x * blockDim.x + threadIdx.x;
    int e = blockIdx.y;
    if (d >= 2 * HID) return;
    long long st = fetch_idx(lab_ev, 0, 2LL * e);
    long long en = fetch_idx(lab_ev, 0, 2LL * e + 1);
    g_evemb[e][d] = (g_prefix[en][d] - g_prefix[st][d]) / (float)(en - st);
}

// ---------------- fold W1 into [A|B|C] ----------------
__global__ void wprep_kernel(const float* __restrict__ w1) {
    int k = blockIdx.x * blockDim.x + threadIdx.x;
    int n = blockIdx.y;
    if (k >= K3) return;
    int seg = k / 768, kk = k - seg * 768;
    const float* r = w1 + (long long)n * 3072;
    float v;
    if (seg == 0) v = r[kk] + r[1536 + kk];
    else if (seg == 1) v = r[768 + kk] - r[1536 + kk];
    else v = r[2304 + kk];
    g_wp[n][k] = v;
}

// ---------------- scores + log-softmax + CE + loss ----------------
__global__ void scores_kernel(const float* __restrict__ w3, const float* __restrict__ b3,
                              const void* __restrict__ labt, float* __restrict__ out,
                              int loss_off) {
    __shared__ float w3s[4][256];
    __shared__ float ce_sh[8];
    int tid = threadIdx.x;
    int wp = tid >> 5, l = tid & 31;
    for (int i = tid; i < 1024; i += 256) w3s[i >> 8][i & 255] = w3[i];
    __syncthreads();

    int p = blockIdx.x * 8 + wp;
    const float* h2r = &g_h2[p][0];
    float hv[8];
#pragma unroll
    for (int k = 0; k < 8; k++) hv[k] = h2r[l + 32 * k];
    float s[4];
#pragma unroll
    for (int j = 0; j < 4; j++) {
        float t = 0.f;
#pragma unroll
        for (int k = 0; k < 8; k++) t += hv[k] * w3s[j][l + 32 * k];
        t += __shfl_xor_sync(0xffffffffu, t, 16);
        t += __shfl_xor_sync(0xffffffffu, t, 8);
        t += __shfl_xor_sync(0xffffffffu, t, 4);
        t += __shfl_xor_sync(0xffffffffu, t, 2);
        t += __shfl_xor_sync(0xffffffffu, t, 1);
        s[j] = t + b3[j];
    }
    if (l == 0) {
        float m = fmaxf(fmaxf(s[0], s[1]), fmaxf(s[2], s[3]));
        float se = expf(s[0] - m) + expf(s[1] - m) + expf(s[2] - m) + expf(s[3] - m);
        float lse = m + logf(se);
        long long y = fetch_idx(labt, 2, p);
        float sy = (y == 0) ? s[0] : (y == 1) ? s[1] : (y == 2) ? s[2] : s[3];
        float* o = out + loss_off + 4LL * p;
        o[0] = s[0]; o[1] = s[1]; o[2] = s[2]; o[3] = s[3];
        ce_sh[wp] = lse - sy;
    }
    __syncthreads();
    if (tid == 0 && loss_off) {
        float t = 0.f;
#pragma unroll
        for (int i = 0; i < 8; i++) t += ce_sh[i];
        atomicAdd(out, t);
    }
}

// ---------------- launch ----------------
extern "C" void kernel_launch(void* const* d_in, const int* in_sizes, int n_in,
                              void* d_out, int out_size) {
    const float* tokemb = (const float*)d_in[0];
    const float* w_ih_f = (const float*)d_in[1];
    const float* w_hh_f = (const float*)d_in[2];
    const float* b_f = (const float*)d_in[3];
    const float* w_ih_b = (const float*)d_in[4];
    const float* w_hh_b = (const float*)d_in[5];
    const float* b_b = (const float*)d_in[6];
    const float* w1 = (const float*)d_in[7];
    const float* b1 = (const float*)d_in[8];
    const float* w2 = (const float*)d_in[9];
    const float* b2 = (const float*)d_in[10];
    const float* w3 = (const float*)d_in[11];
    const float* b3 = (const float*)d_in[12];
    const void* lab_ev = d_in[13];
    const void* pairs = d_in[14];
    const void* labt = d_in[15];
    float* out = (float*)d_out;
    int loss_off = (out_size > 4 * PN_) ? 1 : 0;

    void *p_xg, *p_h1, *p_h2;
    cudaGetSymbolAddress(&p_xg, g_xg);
    cudaGetSymbolAddress(&p_h1, g_h1);
    cudaGetSymbolAddress(&p_h2, g_h2);
    float* xg0 = (float*)p_xg;
    float* xg1 = xg0 + (long long)LSEQ * G4;

    detect_kernel<<<1, 1>>>(lab_ev, pairs, labt);
    init_kernel<<<32, 256>>>(out, loss_off);

    sgemm_nt<<<dim3(G4 / BN, LSEQ / BM), 256>>>(tokemb, w_ih_f, xg0, LSEQ, G4, DIM, nullptr, 0);
    sgemm_nt<<<dim3(G4 / BN, LSEQ / BM), 256>>>(tokemb, w_ih_b, xg1, LSEQ, G4, DIM, nullptr, 0);

    // recurrence: cluster-16 + mbarrier exchange if supported, else fallback
    {
        cudaFuncSetAttribute(lstm_cluster_kernel,
                             cudaFuncAttributeNonPortableClusterSizeAllowed, 1);
        cudaLaunchConfig_t cfg = {};
        cfg.gridDim = dim3(32, 1, 1);
        cfg.blockDim = dim3(256, 1, 1);
        cfg.dynamicSmemBytes = 0;
        cudaLaunchAttribute at[1];
        at[0].id = cudaLaunchAttributeClusterDimension;
        at[0].val.clusterDim.x = 16;
        at[0].val.clusterDim.y = 1;
        at[0].val.clusterDim.z = 1;
        cfg.attrs = at;
        cfg.numAttrs = 1;
        int nclus = 0;
        cudaError_t qe = cudaOccupancyMaxActiveClusters(&nclus, lstm_cluster_kernel, &cfg);
        if (qe == cudaSuccess && nclus >= 2) {
            cudaLaunchKernelEx(&cfg, lstm_cluster_kernel, w_hh_f, b_f, w_hh_b, b_b);
        } else {
            cudaGetLastError();  // clear any sticky query error
            lstm_kernel<<<64, 256>>>(w_hh_f, b_f, w_hh_b, b_b);
        }
    }

    scan1_kernel<<<32, 256>>>();
    scan2_kernel<<<1, 2 * HID>>>();
    scan3_kernel<<<32, 256>>>();
    event_kernel<<<dim3(3, EN_), 256>>>(lab_ev);

    wprep_kernel<<<dim3(9, DIM), 256>>>(w1);
    tgemm_feat<<<dim3(DIM / 128, PN_ / 128), 256>>>(pairs, (float*)p_h1, b1);
    tgemm_nt<<<dim3(256 / 128, PN_ / 128), 256>>>((const float*)p_h1, w2, (float*)p_h2,
                                                  PN_, 256, DIM, b2, 1);

    scores_kernel<<<PN_ / 8, 256>>>(w3, b3, labt, out, loss_off);
}